// round 10
// baseline (speedup 1.0000x reference)
#include <cuda_runtime.h>
#include <cuda_bf16.h>
#include <cuda_fp16.h>
#include <math.h>

// Problem constants (fixed by dataset): N=100000, E=1600000, dims 128->64->32
#define IN_F  128
#define HID_F 64
#define OUT_F 32
#define N_MAX 100000
#define E_MAX 1600000
#define NB_MAX 512

typedef unsigned long long u64;

// ---- packed f32x2 helpers (sm_103a FFMA2 — only reachable via PTX) ----
__device__ __forceinline__ u64 pack2(float lo, float hi) {
    u64 r; asm("mov.b64 %0, {%1, %2};" : "=l"(r) : "f"(lo), "f"(hi)); return r;
}
__device__ __forceinline__ void fma2(u64& d, u64 a, u64 b) {
    asm("fma.rn.f32x2 %0, %1, %2, %0;" : "+l"(d) : "l"(a), "l"(b));
}
__device__ __forceinline__ float2 unpack2(u64 v) {
    float2 f; asm("mov.b64 {%0, %1}, %2;" : "=f"(f.x), "=f"(f.y) : "l"(v)); return f;
}

// ---- device scratch (no cudaMalloc allowed) ----
__device__ int    g_deg    [N_MAX];
__device__ float  g_dinv   [N_MAX];
__device__ int    g_rowstart[N_MAX];
__device__ int    g_cursor [N_MAX];
__device__ int    g_bsum   [NB_MAX];
__device__ int    g_bofs   [NB_MAX];
__device__ int2   g_csr    [E_MAX];                    // packed (src, w)
__device__ __half g_H1h [(size_t)N_MAX * HID_F];       // x@W1, fp16
__device__ float  g_agg1[(size_t)N_MAX * HID_F];       // relu(agg), fp32
__device__ __half g_H2h [(size_t)N_MAX * OUT_F];       // layer2 transform, fp16

// ---------------------------------------------------------------------------
__global__ void k_deg_init(int N) {
    int n = blockIdx.x * blockDim.x + threadIdx.x;
    if (n < N) g_deg[n] = 1;
}

__global__ void k_edge_prep(const int* __restrict__ ei, int E) {
    int e = blockIdx.x * blockDim.x + threadIdx.x;
    if (e < E) atomicAdd(&g_deg[ei[E + e]], 1);
}

__global__ __launch_bounds__(256) void k_scan_a(int N) {
    __shared__ int sh[256];
    int t = threadIdx.x;
    int n = blockIdx.x * 256 + t;
    int deg = (n < N) ? g_deg[n] : 1;
    if (n < N) g_dinv[n] = rsqrtf((float)deg);
    sh[t] = (n < N) ? (deg - 1) : 0;
    __syncthreads();
    for (int off = 128; off > 0; off >>= 1) {
        if (t < off) sh[t] += sh[t + off];
        __syncthreads();
    }
    if (t == 0) g_bsum[blockIdx.x] = sh[0];
}

__global__ __launch_bounds__(512) void k_scan_b(int NB) {
    __shared__ int sh[512];
    int t = threadIdx.x;
    int v = (t < NB) ? g_bsum[t] : 0;
    sh[t] = v;
    __syncthreads();
    for (int off = 1; off < 512; off <<= 1) {
        int add = (t >= off) ? sh[t - off] : 0;
        __syncthreads();
        sh[t] += add;
        __syncthreads();
    }
    if (t < NB) g_bofs[t] = sh[t] - v;
}

__global__ __launch_bounds__(256) void k_scan_c(int N) {
    __shared__ int sh[256];
    int t = threadIdx.x;
    int n = blockIdx.x * 256 + t;
    int v = (n < N) ? (g_deg[n] - 1) : 0;
    sh[t] = v;
    __syncthreads();
    for (int off = 1; off < 256; off <<= 1) {
        int add = (t >= off) ? sh[t - off] : 0;
        __syncthreads();
        sh[t] += add;
        __syncthreads();
    }
    if (n < N) {
        int excl = sh[t] - v + g_bofs[blockIdx.x];
        g_rowstart[n] = excl;
        g_cursor[n]   = excl;
    }
}

__global__ void k_fill(const int* __restrict__ ei, int E) {
    int e = blockIdx.x * blockDim.x + threadIdx.x;
    if (e < E) {
        int s = ei[e];
        int d = ei[E + e];
        int pos = atomicAdd(&g_cursor[d], 1);
        g_csr[pos] = make_int2(s, __float_as_int(g_dinv[s] * g_dinv[d]));
    }
}

// ---------------------------------------------------------------------------
// GEMM1: 128x64 block, 256 threads, 8x4 micro-tile, row-pair FFMA2.
// Software-pipelined: next x chunk prefetched into regs during compute.
// Output stored fp16.
#define KC 32
#define XT_STRIDE 132
__global__ __launch_bounds__(256) void k_gemm1(const float* __restrict__ x,
                                               const float* __restrict__ W,
                                               int N) {
    __shared__ float Ws[IN_F * HID_F];      // 32 KB
    __shared__ float xsT[KC * XT_STRIDE];   // ~16.5 KB
    int t  = threadIdx.x;
    int ty = t >> 4;
    int tx = t & 15;
    int row0 = blockIdx.x * 128;
    int r0 = t >> 3;       // transpose: this thread's base row
    int kq = t & 7;        // transpose: this thread's k-quad

    for (int i = t; i < IN_F * HID_F / 4; i += 256)
        ((float4*)Ws)[i] = ((const float4*)W)[i];

    // prefetch chunk 0
    float4 pf[4];
    #pragma unroll
    for (int j = 0; j < 4; ++j) {
        int row = row0 + r0 + 32 * j;
        pf[j] = (row < N) ? *(const float4*)&x[(size_t)row * IN_F + kq * 4]
                          : make_float4(0.f, 0.f, 0.f, 0.f);
    }

    u64 acc[4][4];
    #pragma unroll
    for (int p = 0; p < 4; ++p)
        #pragma unroll
        for (int c = 0; c < 4; ++c) acc[p][c] = 0ull;

    for (int kc = 0; kc < IN_F; kc += KC) {
        __syncthreads();
        #pragma unroll
        for (int j = 0; j < 4; ++j) {
            int r = r0 + 32 * j;
            xsT[(kq * 4 + 0) * XT_STRIDE + r] = pf[j].x;
            xsT[(kq * 4 + 1) * XT_STRIDE + r] = pf[j].y;
            xsT[(kq * 4 + 2) * XT_STRIDE + r] = pf[j].z;
            xsT[(kq * 4 + 3) * XT_STRIDE + r] = pf[j].w;
        }
        __syncthreads();
        if (kc + KC < IN_F) {
            #pragma unroll
            for (int j = 0; j < 4; ++j) {
                int row = row0 + r0 + 32 * j;
                pf[j] = (row < N) ? *(const float4*)&x[(size_t)row * IN_F + kc + KC + kq * 4]
                                  : make_float4(0.f, 0.f, 0.f, 0.f);
            }
        }
        #pragma unroll
        for (int k = 0; k < KC; ++k) {
            const float* xrow = &xsT[k * XT_STRIDE + ty * 8];
            float4 xa = *(const float4*)&xrow[0];
            float4 xb = *(const float4*)&xrow[4];
            u64 x0 = pack2(xa.x, xa.y);
            u64 x1 = pack2(xa.z, xa.w);
            u64 x2 = pack2(xb.x, xb.y);
            u64 x3 = pack2(xb.z, xb.w);
            float4 w = *(const float4*)&Ws[(kc + k) * HID_F + tx * 4];
            u64 wb0 = pack2(w.x, w.x);
            u64 wb1 = pack2(w.y, w.y);
            u64 wb2 = pack2(w.z, w.z);
            u64 wb3 = pack2(w.w, w.w);
            fma2(acc[0][0], x0, wb0); fma2(acc[0][1], x0, wb1);
            fma2(acc[0][2], x0, wb2); fma2(acc[0][3], x0, wb3);
            fma2(acc[1][0], x1, wb0); fma2(acc[1][1], x1, wb1);
            fma2(acc[1][2], x1, wb2); fma2(acc[1][3], x1, wb3);
            fma2(acc[2][0], x2, wb0); fma2(acc[2][1], x2, wb1);
            fma2(acc[2][2], x2, wb2); fma2(acc[2][3], x2, wb3);
            fma2(acc[3][0], x3, wb0); fma2(acc[3][1], x3, wb1);
            fma2(acc[3][2], x3, wb2); fma2(acc[3][3], x3, wb3);
        }
    }
    #pragma unroll
    for (int p = 0; p < 4; ++p) {
        float2 c0 = unpack2(acc[p][0]);
        float2 c1 = unpack2(acc[p][1]);
        float2 c2 = unpack2(acc[p][2]);
        float2 c3 = unpack2(acc[p][3]);
        int ra = row0 + ty * 8 + 2 * p;
        int rb = ra + 1;
        if (ra < N) {
            __half2 h01 = __floats2half2_rn(c0.x, c1.x);
            __half2 h23 = __floats2half2_rn(c2.x, c3.x);
            *(__half2*)&g_H1h[(size_t)ra * HID_F + tx * 4]     = h01;
            *(__half2*)&g_H1h[(size_t)ra * HID_F + tx * 4 + 2] = h23;
        }
        if (rb < N) {
            __half2 h01 = __floats2half2_rn(c0.y, c1.y);
            __half2 h23 = __floats2half2_rn(c2.y, c3.y);
            *(__half2*)&g_H1h[(size_t)rb * HID_F + tx * 4]     = h01;
            *(__half2*)&g_H1h[(size_t)rb * HID_F + tx * 4 + 2] = h23;
        }
    }
}

// GEMM2: H2[N,32] = agg1[N,64] @ W2[64,32]; fp32 in, fp16 out.
__global__ __launch_bounds__(256) void k_gemm2(const float* __restrict__ W, int N) {
    __shared__ float Ws[HID_F * OUT_F];
    __shared__ float xs[32 * HID_F];
    int t = threadIdx.x;
    for (int i = t; i < HID_F * OUT_F; i += 256) Ws[i] = W[i];

    int row0 = blockIdx.x * 32;
    int rows = N - row0; if (rows > 32) rows = 32;

    const float4* xg  = (const float4*)(g_agg1 + (size_t)row0 * HID_F);
    float4*       xs4 = (float4*)xs;
    const int NV = 32 * HID_F / 4;
    for (int i = t; i < NV; i += 256) {
        int r = i / (HID_F / 4);
        xs4[i] = (r < rows) ? xg[i] : make_float4(0.f, 0.f, 0.f, 0.f);
    }
    __syncthreads();

    int r = t >> 3;
    int g = (t & 7) * 4;
    if (r < rows) {
        u64 a01 = 0ull, a23 = 0ull;
        #pragma unroll 16
        for (int k = 0; k < HID_F; ++k) {
            float xv = xs[r * HID_F + k];
            u64 xp  = pack2(xv, xv);
            u64 w01 = *(const u64*)&Ws[k * OUT_F + g];
            u64 w23 = *(const u64*)&Ws[k * OUT_F + g + 2];
            fma2(a01, xp, w01);
            fma2(a23, xp, w23);
        }
        float2 f01 = unpack2(a01);
        float2 f23 = unpack2(a23);
        __half2 h01 = __floats2half2_rn(f01.x, f01.y);
        __half2 h23 = __floats2half2_rn(f23.x, f23.y);
        *(__half2*)&g_H2h[(size_t)(row0 + r) * OUT_F + g]     = h01;
        *(__half2*)&g_H2h[(size_t)(row0 + r) * OUT_F + g + 2] = h23;
    }
}

// ---------------------------------------------------------------------------
// Gather1: half-warp per node, 16 lanes x 4 feats (fp16: 8B/lane/edge).
__global__ __launch_bounds__(256) void k_gather1(const float* __restrict__ b1, int N) {
    int w    = (blockIdx.x * blockDim.x + threadIdx.x) >> 5;
    int lane = threadIdx.x & 31;
    int h    = lane >> 4;
    int hl   = lane & 15;
    int n    = 2 * w + h;
    bool active = (n < N);
    int nn = active ? n : 0;

    float dn = g_dinv[nn];
    float c  = dn * dn;
    __half2 sh01 = *(const __half2*)&g_H1h[(size_t)nn * HID_F + hl * 4];
    __half2 sh23 = *(const __half2*)&g_H1h[(size_t)nn * HID_F + hl * 4 + 2];
    float2 s01 = __half22float2(sh01);
    float2 s23 = __half22float2(sh23);
    float4 bb = *(const float4*)&b1[hl * 4];
    u64 acc0 = pack2(fmaf(s01.x, c, bb.x), fmaf(s01.y, c, bb.y));
    u64 acc1 = pack2(fmaf(s23.x, c, bb.z), fmaf(s23.y, c, bb.w));

    int start = active ? g_rowstart[nn] : 0;
    int cnt   = active ? (g_deg[nn] - 1) : 0;
    int omax  = __shfl_xor_sync(0xffffffffu, cnt, 16);
    int maxcnt = cnt > omax ? cnt : omax;

    for (int base = 0; base < maxcnt; base += 16) {
        int  sl = 0; float wl = 0.f;
        if (base + hl < cnt) {
            int2 p = g_csr[start + base + hl];
            sl = p.x; wl = __int_as_float(p.y);
        }
        int remw = maxcnt - base; if (remw > 16) remw = 16;
        int remh = cnt - base;
        #pragma unroll 4
        for (int k = 0; k < remw; ++k) {
            int   sk = __shfl_sync(0xffffffffu, sl, h * 16 + k);
            float wk = __shfl_sync(0xffffffffu, wl, h * 16 + k);
            if (k < remh) {
                uint2 hv = *(const uint2*)&g_H1h[(size_t)sk * HID_F + hl * 4];
                float2 v01 = __half22float2(*(__half2*)&hv.x);
                float2 v23 = __half22float2(*(__half2*)&hv.y);
                u64 wp = pack2(wk, wk);
                fma2(acc0, wp, pack2(v01.x, v01.y));
                fma2(acc1, wp, pack2(v23.x, v23.y));
            }
        }
    }
    if (active) {
        float2 a = unpack2(acc0), b = unpack2(acc1);
        *(float4*)&g_agg1[(size_t)n * HID_F + hl * 4] =
            make_float4(fmaxf(a.x, 0.f), fmaxf(a.y, 0.f),
                        fmaxf(b.x, 0.f), fmaxf(b.y, 0.f));
    }
}

// Gather2: half-warp per node, 16 lanes x 2 feats (fp16: 4B/lane/edge).
__global__ __launch_bounds__(256) void k_gather2(const float* __restrict__ b2,
                                                 float* __restrict__ out, int N) {
    int w    = (blockIdx.x * blockDim.x + threadIdx.x) >> 5;
    int lane = threadIdx.x & 31;
    int h    = lane >> 4;
    int hl   = lane & 15;
    int n    = 2 * w + h;
    bool active = (n < N);
    int nn = active ? n : 0;

    float dn = g_dinv[nn];
    float c  = dn * dn;
    float2 sv = __half22float2(*(const __half2*)&g_H2h[(size_t)nn * OUT_F + hl * 2]);
    float2 bb = *(const float2*)&b2[hl * 2];
    u64 acc = pack2(fmaf(sv.x, c, bb.x), fmaf(sv.y, c, bb.y));

    int start = active ? g_rowstart[nn] : 0;
    int cnt   = active ? (g_deg[nn] - 1) : 0;
    int omax  = __shfl_xor_sync(0xffffffffu, cnt, 16);
    int maxcnt = cnt > omax ? cnt : omax;

    for (int base = 0; base < maxcnt; base += 16) {
        int  sl = 0; float wl = 0.f;
        if (base + hl < cnt) {
            int2 p = g_csr[start + base + hl];
            sl = p.x; wl = __int_as_float(p.y);
        }
        int remw = maxcnt - base; if (remw > 16) remw = 16;
        int remh = cnt - base;
        #pragma unroll 4
        for (int k = 0; k < remw; ++k) {
            int   sk = __shfl_sync(0xffffffffu, sl, h * 16 + k);
            float wk = __shfl_sync(0xffffffffu, wl, h * 16 + k);
            if (k < remh) {
                float2 v = __half22float2(*(const __half2*)&g_H2h[(size_t)sk * OUT_F + hl * 2]);
                fma2(acc, pack2(wk, wk), pack2(v.x, v.y));
            }
        }
    }
    if (active) {
        float2 a = unpack2(acc);
        *(float2*)&out[(size_t)n * OUT_F + hl * 2] = a;
    }
}

// ---------------------------------------------------------------------------
extern "C" void kernel_launch(void* const* d_in, const int* in_sizes, int n_in,
                              void* d_out, int out_size) {
    const float* x  = (const float*)d_in[0];
    const int*   ei = (const int*)d_in[1];      // int32 (JAX x64 disabled)
    const float* W1 = (const float*)d_in[2];
    const float* b1 = (const float*)d_in[3];
    const float* W2 = (const float*)d_in[4];
    const float* b2 = (const float*)d_in[5];
    float*       out = (float*)d_out;

    const int N = in_sizes[0] / IN_F;     // 100000
    const int E = in_sizes[1] / 2;        // 1600000
    const int NB = (N + 255) / 256;

    const int T = 256;
    k_deg_init <<<(N + T - 1) / T, T>>>(N);
    k_edge_prep<<<(E + T - 1) / T, T>>>(ei, E);
    k_scan_a<<<NB, 256>>>(N);
    k_gemm1  <<<(N + 127) / 128, 256>>>(x, W1, N);  // 4th launch (profiled)
    k_scan_b<<<1, 512>>>(NB);
    k_scan_c<<<NB, 256>>>(N);
    k_fill  <<<(E + T - 1) / T, T>>>(ei, E);

    k_gather1<<<(N + 15) / 16, 256>>>(b1, N);

    k_gemm2  <<<(N + 31) / 32, 256>>>(W2, N);
    k_gather2<<<(N + 15) / 16, 256>>>(b2, out, N);
}

// round 11
// speedup vs baseline: 1.0574x; 1.0574x over previous
#include <cuda_runtime.h>
#include <cuda_bf16.h>
#include <math.h>

// Problem constants (fixed by dataset): N=100000, E=1600000, dims 128->64->32
#define IN_F  128
#define HID_F 64
#define OUT_F 32
#define N_MAX 100000
#define E_MAX 1600000
#define NB_MAX 512

typedef unsigned long long u64;
typedef unsigned int u32;

// ---- packed f32x2 helpers (sm_103a FFMA2 via PTX) ----
__device__ __forceinline__ u64 pack2(float lo, float hi) {
    u64 r; asm("mov.b64 %0, {%1, %2};" : "=l"(r) : "f"(lo), "f"(hi)); return r;
}
__device__ __forceinline__ void fma2(u64& d, u64 a, u64 b) {
    asm("fma.rn.f32x2 %0, %1, %2, %0;" : "+l"(d) : "l"(a), "l"(b));
}
__device__ __forceinline__ float2 unpack2(u64 v) {
    float2 f; asm("mov.b64 {%0, %1}, %2;" : "=f"(f.x), "=f"(f.y) : "l"(v)); return f;
}
__device__ __forceinline__ u32 f2tf32(float f) {
    u32 r; asm("cvt.rna.tf32.f32 %0, %1;" : "=r"(r) : "f"(f)); return r;
}

// ---- device scratch (no cudaMalloc allowed) ----
__device__ int   g_deg    [N_MAX];
__device__ float g_dinv   [N_MAX];
__device__ int   g_rowstart[N_MAX];
__device__ int   g_cursor [N_MAX];
__device__ int   g_bsum   [NB_MAX];
__device__ int   g_bofs   [NB_MAX];
__device__ int2  g_csr    [E_MAX];                 // packed (src, w)
__device__ float g_H1  [(size_t)N_MAX * HID_F];    // x @ W1 (fp32)
__device__ float g_agg1[(size_t)N_MAX * HID_F];    // relu(agg), fp32
__device__ float g_H2  [(size_t)N_MAX * OUT_F];    // fp32

// ---------------------------------------------------------------------------
__global__ void k_deg_init(int N) {
    int n = blockIdx.x * blockDim.x + threadIdx.x;
    if (n < N) g_deg[n] = 1;
}

__global__ void k_edge_prep(const int* __restrict__ ei, int E) {
    int e = blockIdx.x * blockDim.x + threadIdx.x;
    if (e < E) atomicAdd(&g_deg[ei[E + e]], 1);
}

__global__ __launch_bounds__(256) void k_scan_a(int N) {
    __shared__ int sh[256];
    int t = threadIdx.x;
    int n = blockIdx.x * 256 + t;
    int deg = (n < N) ? g_deg[n] : 1;
    if (n < N) g_dinv[n] = rsqrtf((float)deg);
    sh[t] = (n < N) ? (deg - 1) : 0;
    __syncthreads();
    for (int off = 128; off > 0; off >>= 1) {
        if (t < off) sh[t] += sh[t + off];
        __syncthreads();
    }
    if (t == 0) g_bsum[blockIdx.x] = sh[0];
}

__global__ __launch_bounds__(512) void k_scan_b(int NB) {
    __shared__ int sh[512];
    int t = threadIdx.x;
    int v = (t < NB) ? g_bsum[t] : 0;
    sh[t] = v;
    __syncthreads();
    for (int off = 1; off < 512; off <<= 1) {
        int add = (t >= off) ? sh[t - off] : 0;
        __syncthreads();
        sh[t] += add;
        __syncthreads();
    }
    if (t < NB) g_bofs[t] = sh[t] - v;
}

__global__ __launch_bounds__(256) void k_scan_c(int N) {
    __shared__ int sh[256];
    int t = threadIdx.x;
    int n = blockIdx.x * 256 + t;
    int v = (n < N) ? (g_deg[n] - 1) : 0;
    sh[t] = v;
    __syncthreads();
    for (int off = 1; off < 256; off <<= 1) {
        int add = (t >= off) ? sh[t - off] : 0;
        __syncthreads();
        sh[t] += add;
        __syncthreads();
    }
    if (n < N) {
        int excl = sh[t] - v + g_bofs[blockIdx.x];
        g_rowstart[n] = excl;
        g_cursor[n]   = excl;
    }
}

__global__ void k_fill(const int* __restrict__ ei, int E) {
    int e = blockIdx.x * blockDim.x + threadIdx.x;
    if (e < E) {
        int s = ei[e];
        int d = ei[E + e];
        int pos = atomicAdd(&g_cursor[d], 1);
        g_csr[pos] = make_int2(s, __float_as_int(g_dinv[s] * g_dinv[d]));
    }
}

// ---------------------------------------------------------------------------
// GEMM1 (tensor cores): H1[N,64] = x[N,128] @ W1[128,64] via
// mma.sync.m16n8k8 tf32. 256 threads = 8 warps; each warp: 16 rows x 64 cols.
// A fragments LDG'd directly (warp-private rows, L1-resident); W1 staged in
// smem with stride 72 -> B-fragment LDS conflict-free (bank = 8*gc+gr).
#define WS_STRIDE 72
__global__ __launch_bounds__(256) void k_gemm1(const float* __restrict__ x,
                                               const float* __restrict__ W,
                                               int N) {
    __shared__ float Ws[IN_F * WS_STRIDE];   // 36.9 KB, [k][72]
    int t = threadIdx.x;
    // stage W1: [128][64] -> [128][72]
    for (int i = t; i < IN_F * (HID_F / 4); i += 256) {
        int k  = i >> 4;
        int nq = i & 15;
        float4 v = ((const float4*)W)[i];
        *(float4*)&Ws[k * WS_STRIDE + nq * 4] = v;
    }
    __syncthreads();

    int warp = t >> 5, lane = t & 31;
    int gr = lane >> 2;      // 0..7
    int gc = lane & 3;       // 0..3
    int row_base = blockIdx.x * 128 + warp * 16;
    int r0 = row_base + gr;
    int r1 = r0 + 8;
    bool v0 = (r0 < N), v1 = (r1 < N);

    float acc[8][4];
    #pragma unroll
    for (int nt = 0; nt < 8; ++nt)
        #pragma unroll
        for (int c = 0; c < 4; ++c) acc[nt][c] = 0.f;

    const float* xr0 = x + (size_t)r0 * IN_F;
    const float* xr1 = x + (size_t)r1 * IN_F;

    #pragma unroll
    for (int k0 = 0; k0 < IN_F; k0 += 8) {
        u32 a0 = f2tf32(v0 ? xr0[k0 + gc]     : 0.f);
        u32 a1 = f2tf32(v1 ? xr1[k0 + gc]     : 0.f);
        u32 a2 = f2tf32(v0 ? xr0[k0 + gc + 4] : 0.f);
        u32 a3 = f2tf32(v1 ? xr1[k0 + gc + 4] : 0.f);
        #pragma unroll
        for (int nt = 0; nt < 8; ++nt) {
            int n0 = nt * 8;
            u32 b0 = f2tf32(Ws[(k0 + gc) * WS_STRIDE + n0 + gr]);
            u32 b1 = f2tf32(Ws[(k0 + gc + 4) * WS_STRIDE + n0 + gr]);
            asm("mma.sync.aligned.m16n8k8.row.col.f32.tf32.tf32.f32 "
                "{%0,%1,%2,%3}, {%4,%5,%6,%7}, {%8,%9}, {%0,%1,%2,%3};"
                : "+f"(acc[nt][0]), "+f"(acc[nt][1]),
                  "+f"(acc[nt][2]), "+f"(acc[nt][3])
                : "r"(a0), "r"(a1), "r"(a2), "r"(a3), "r"(b0), "r"(b1));
        }
    }
    // store: c0 at (gr, 2gc), c1 (gr, 2gc+1), c2 (gr+8, 2gc), c3 (gr+8, 2gc+1)
    #pragma unroll
    for (int nt = 0; nt < 8; ++nt) {
        int cb = nt * 8 + 2 * gc;
        if (v0) *(float2*)&g_H1[(size_t)r0 * HID_F + cb] = make_float2(acc[nt][0], acc[nt][1]);
        if (v1) *(float2*)&g_H1[(size_t)r1 * HID_F + cb] = make_float2(acc[nt][2], acc[nt][3]);
    }
}

// GEMM2: H2[N,32] = agg1[N,64] @ W2[64,32]; col-pair packed FFMA2 (fp32)
__global__ __launch_bounds__(256) void k_gemm2(const float* __restrict__ W, int N) {
    __shared__ float Ws[HID_F * OUT_F];
    __shared__ float xs[32 * HID_F];
    int t = threadIdx.x;
    for (int i = t; i < HID_F * OUT_F; i += 256) Ws[i] = W[i];

    int row0 = blockIdx.x * 32;
    int rows = N - row0; if (rows > 32) rows = 32;

    const float4* xg  = (const float4*)(g_agg1 + (size_t)row0 * HID_F);
    float4*       xs4 = (float4*)xs;
    const int NV = 32 * HID_F / 4;
    for (int i = t; i < NV; i += 256) {
        int r = i / (HID_F / 4);
        xs4[i] = (r < rows) ? xg[i] : make_float4(0.f, 0.f, 0.f, 0.f);
    }
    __syncthreads();

    int r = t >> 3;
    int g = (t & 7) * 4;
    if (r < rows) {
        u64 a01 = 0ull, a23 = 0ull;
        #pragma unroll 16
        for (int k = 0; k < HID_F; ++k) {
            float xv = xs[r * HID_F + k];
            u64 xp  = pack2(xv, xv);
            u64 w01 = *(const u64*)&Ws[k * OUT_F + g];
            u64 w23 = *(const u64*)&Ws[k * OUT_F + g + 2];
            fma2(a01, xp, w01);
            fma2(a23, xp, w23);
        }
        float2 f01 = unpack2(a01);
        float2 f23 = unpack2(a23);
        float* out = g_H2 + (size_t)(row0 + r) * OUT_F + g;
        *(float4*)out = make_float4(f01.x, f01.y, f23.x, f23.y);
    }
}

// ---------------------------------------------------------------------------
// Gather1: half-warp per node (2 nodes/warp), 16 lanes x float4 (fp32).
__global__ __launch_bounds__(256) void k_gather1(const float* __restrict__ b1, int N) {
    int w    = (blockIdx.x * blockDim.x + threadIdx.x) >> 5;
    int lane = threadIdx.x & 31;
    int h    = lane >> 4;
    int hl   = lane & 15;
    int n    = 2 * w + h;
    bool active = (n < N);
    int nn = active ? n : 0;

    float dn = g_dinv[nn];
    float c  = dn * dn;
    float4 hv = *(const float4*)&g_H1[(size_t)nn * HID_F + hl * 4];
    float4 bb = *(const float4*)&b1[hl * 4];
    u64 acc0 = pack2(fmaf(hv.x, c, bb.x), fmaf(hv.y, c, bb.y));
    u64 acc1 = pack2(fmaf(hv.z, c, bb.z), fmaf(hv.w, c, bb.w));

    int start = active ? g_rowstart[nn] : 0;
    int cnt   = active ? (g_deg[nn] - 1) : 0;
    int omax  = __shfl_xor_sync(0xffffffffu, cnt, 16);
    int maxcnt = cnt > omax ? cnt : omax;

    for (int base = 0; base < maxcnt; base += 16) {
        int  sl = 0; float wl = 0.f;
        if (base + hl < cnt) {
            int2 p = g_csr[start + base + hl];
            sl = p.x; wl = __int_as_float(p.y);
        }
        int remw = maxcnt - base; if (remw > 16) remw = 16;
        int remh = cnt - base;
        #pragma unroll 4
        for (int k = 0; k < remw; ++k) {
            int   sk = __shfl_sync(0xffffffffu, sl, h * 16 + k);
            float wk = __shfl_sync(0xffffffffu, wl, h * 16 + k);
            if (k < remh) {
                float4 v = *(const float4*)&g_H1[(size_t)sk * HID_F + hl * 4];
                u64 wp = pack2(wk, wk);
                fma2(acc0, wp, pack2(v.x, v.y));
                fma2(acc1, wp, pack2(v.z, v.w));
            }
        }
    }
    if (active) {
        float2 a = unpack2(acc0), b = unpack2(acc1);
        *(float4*)&g_agg1[(size_t)n * HID_F + hl * 4] =
            make_float4(fmaxf(a.x, 0.f), fmaxf(a.y, 0.f),
                        fmaxf(b.x, 0.f), fmaxf(b.y, 0.f));
    }
}

// Gather2: half-warp per node, 16 lanes x float2 (fp32), writes d_out.
__global__ __launch_bounds__(256) void k_gather2(const float* __restrict__ b2,
                                                 float* __restrict__ out, int N) {
    int w    = (blockIdx.x * blockDim.x + threadIdx.x) >> 5;
    int lane = threadIdx.x & 31;
    int h    = lane >> 4;
    int hl   = lane & 15;
    int n    = 2 * w + h;
    bool active = (n < N);
    int nn = active ? n : 0;

    float dn = g_dinv[nn];
    float c  = dn * dn;
    float2 hv = *(const float2*)&g_H2[(size_t)nn * OUT_F + hl * 2];
    float2 bb = *(const float2*)&b2[hl * 2];
    u64 acc = pack2(fmaf(hv.x, c, bb.x), fmaf(hv.y, c, bb.y));

    int start = active ? g_rowstart[nn] : 0;
    int cnt   = active ? (g_deg[nn] - 1) : 0;
    int omax  = __shfl_xor_sync(0xffffffffu, cnt, 16);
    int maxcnt = cnt > omax ? cnt : omax;

    for (int base = 0; base < maxcnt; base += 16) {
        int  sl = 0; float wl = 0.f;
        if (base + hl < cnt) {
            int2 p = g_csr[start + base + hl];
            sl = p.x; wl = __int_as_float(p.y);
        }
        int remw = maxcnt - base; if (remw > 16) remw = 16;
        int remh = cnt - base;
        #pragma unroll 4
        for (int k = 0; k < remw; ++k) {
            int   sk = __shfl_sync(0xffffffffu, sl, h * 16 + k);
            float wk = __shfl_sync(0xffffffffu, wl, h * 16 + k);
            if (k < remh) {
                u64 v = *(const u64*)&g_H2[(size_t)sk * OUT_F + hl * 2];
                fma2(acc, pack2(wk, wk), v);
            }
        }
    }
    if (active) {
        float2 a = unpack2(acc);
        *(float2*)&out[(size_t)n * OUT_F + hl * 2] = a;
    }
}

// ---------------------------------------------------------------------------
extern "C" void kernel_launch(void* const* d_in, const int* in_sizes, int n_in,
                              void* d_out, int out_size) {
    const float* x  = (const float*)d_in[0];
    const int*   ei = (const int*)d_in[1];      // int32 (JAX x64 disabled)
    const float* W1 = (const float*)d_in[2];
    const float* b1 = (const float*)d_in[3];
    const float* W2 = (const float*)d_in[4];
    const float* b2 = (const float*)d_in[5];
    float*       out = (float*)d_out;

    const int N = in_sizes[0] / IN_F;     // 100000
    const int E = in_sizes[1] / 2;        // 1600000
    const int NB = (N + 255) / 256;

    const int T = 256;
    k_deg_init <<<(N + T - 1) / T, T>>>(N);
    k_edge_prep<<<(E + T - 1) / T, T>>>(ei, E);
    k_scan_a<<<NB, 256>>>(N);
    k_gemm1  <<<(N + 127) / 128, 256>>>(x, W1, N);  // 4th launch (profiled)
    k_scan_b<<<1, 512>>>(NB);
    k_scan_c<<<NB, 256>>>(N);
    k_fill  <<<(E + T - 1) / T, T>>>(ei, E);

    k_gather1<<<(N + 15) / 16, 256>>>(b1, N);

    k_gemm2  <<<(N + 31) / 32, 256>>>(W2, N);
    k_gather2<<<(N + 15) / 16, 256>>>(b2, out, N);
}

// round 13
// speedup vs baseline: 1.4526x; 1.3737x over previous
#include <cuda_runtime.h>
#include <cuda_bf16.h>
#include <cuda_fp16.h>
#include <math.h>

// Problem constants (fixed by dataset): N=100000, E=1600000, dims 128->64->32
#define IN_F  128
#define HID_F 64
#define OUT_F 32
#define N_MAX 100000
#define E_MAX 1600000
#define NB_MAX 512

typedef unsigned long long u64;

// ---- packed f32x2 helpers (sm_103a FFMA2 via PTX) ----
__device__ __forceinline__ u64 pack2(float lo, float hi) {
    u64 r; asm("mov.b64 %0, {%1, %2};" : "=l"(r) : "f"(lo), "f"(hi)); return r;
}
__device__ __forceinline__ void fma2(u64& d, u64 a, u64 b) {
    asm("fma.rn.f32x2 %0, %1, %2, %0;" : "+l"(d) : "l"(a), "l"(b));
}
__device__ __forceinline__ float2 unpack2(u64 v) {
    float2 f; asm("mov.b64 {%0, %1}, %2;" : "=f"(f.x), "=f"(f.y) : "l"(v)); return f;
}

// ---- device scratch (no cudaMalloc allowed) ----
// g_deg starts zero (static init) and is re-zeroed by gather2 (last reader)
// each launch, so every launch sees a clean histogram.
__device__ int    g_deg    [N_MAX];                 // in-degree (self-loop excluded)
__device__ float  g_dinv   [N_MAX];
__device__ int    g_rowstart[N_MAX];
__device__ int    g_cursor [N_MAX];
__device__ int    g_bsum   [NB_MAX];
__device__ int    g_bofs   [NB_MAX];
__device__ int2   g_csr    [E_MAX];                 // packed (src, w)
__device__ __half g_H1h [(size_t)N_MAX * HID_F];    // x @ W1 (fp16)
__device__ float  g_agg1[(size_t)N_MAX * HID_F];    // relu(agg), fp32
__device__ float  g_H2  [(size_t)N_MAX * OUT_F];    // fp32

// ---------------------------------------------------------------------------
__global__ void k_edge_prep(const int* __restrict__ ei, int E) {
    int e = blockIdx.x * blockDim.x + threadIdx.x;
    if (e < E) atomicAdd(&g_deg[ei[E + e]], 1);
}

// SA: per-block indegree sums + dinv (deg = indeg + 1 self-loop)
__global__ __launch_bounds__(256) void k_scan_a(int N) {
    __shared__ int sh[256];
    int t = threadIdx.x;
    int n = blockIdx.x * 256 + t;
    int cnt = (n < N) ? g_deg[n] : 0;
    if (n < N) g_dinv[n] = rsqrtf((float)(cnt + 1));
    sh[t] = cnt;
    __syncthreads();
    for (int off = 128; off > 0; off >>= 1) {
        if (t < off) sh[t] += sh[t + off];
        __syncthreads();
    }
    if (t == 0) g_bsum[blockIdx.x] = sh[0];
}

__global__ __launch_bounds__(512) void k_scan_b(int NB) {
    __shared__ int sh[512];
    int t = threadIdx.x;
    int v = (t < NB) ? g_bsum[t] : 0;
    sh[t] = v;
    __syncthreads();
    for (int off = 1; off < 512; off <<= 1) {
        int add = (t >= off) ? sh[t - off] : 0;
        __syncthreads();
        sh[t] += add;
        __syncthreads();
    }
    if (t < NB) g_bofs[t] = sh[t] - v;
}

__global__ __launch_bounds__(256) void k_scan_c(int N) {
    __shared__ int sh[256];
    int t = threadIdx.x;
    int n = blockIdx.x * 256 + t;
    int v = (n < N) ? g_deg[n] : 0;
    sh[t] = v;
    __syncthreads();
    for (int off = 1; off < 256; off <<= 1) {
        int add = (t >= off) ? sh[t - off] : 0;
        __syncthreads();
        sh[t] += add;
        __syncthreads();
    }
    if (n < N) {
        int excl = sh[t] - v + g_bofs[blockIdx.x];
        g_rowstart[n] = excl;
        g_cursor[n]   = excl;
    }
}

__global__ void k_fill(const int* __restrict__ ei, int E) {
    int e = blockIdx.x * blockDim.x + threadIdx.x;
    if (e < E) {
        int s = ei[e];
        int d = ei[E + e];
        int pos = atomicAdd(&g_cursor[d], 1);
        g_csr[pos] = make_int2(s, __float_as_int(g_dinv[s] * g_dinv[d]));
    }
}

// ---------------------------------------------------------------------------
// GEMM1 (R8-proven FFMA2 version): 128x64 block, 256 threads, 8x4 micro-tile,
// row-pair packed accumulators. Only change vs R8: fp16 output store.
#define KC 32
#define XT_STRIDE 132
__global__ __launch_bounds__(256) void k_gemm1(const float* __restrict__ x,
                                               const float* __restrict__ W,
                                               int N) {
    __shared__ float Ws[IN_F * HID_F];      // 32 KB
    __shared__ float xsT[KC * XT_STRIDE];   // ~16.5 KB
    int t  = threadIdx.x;
    int ty = t >> 4;
    int tx = t & 15;
    int row0 = blockIdx.x * 128;

    for (int i = t; i < IN_F * HID_F / 4; i += 256)
        ((float4*)Ws)[i] = ((const float4*)W)[i];

    u64 acc[4][4];
    #pragma unroll
    for (int p = 0; p < 4; ++p)
        #pragma unroll
        for (int c = 0; c < 4; ++c) acc[p][c] = 0ull;

    for (int kc = 0; kc < IN_F; kc += KC) {
        __syncthreads();
        for (int i = t; i < 128 * (KC / 4); i += 256) {
            int r  = i >> 3;
            int kq = i & 7;
            int row = row0 + r;
            float4 v = make_float4(0.f, 0.f, 0.f, 0.f);
            if (row < N) v = *(const float4*)&x[(size_t)row * IN_F + kc + kq * 4];
            xsT[(kq * 4 + 0) * XT_STRIDE + r] = v.x;
            xsT[(kq * 4 + 1) * XT_STRIDE + r] = v.y;
            xsT[(kq * 4 + 2) * XT_STRIDE + r] = v.z;
            xsT[(kq * 4 + 3) * XT_STRIDE + r] = v.w;
        }
        __syncthreads();
        #pragma unroll
        for (int k = 0; k < KC; ++k) {
            const float* xrow = &xsT[k * XT_STRIDE + ty * 8];
            float4 xa = *(const float4*)&xrow[0];
            float4 xb = *(const float4*)&xrow[4];
            u64 x0 = pack2(xa.x, xa.y);
            u64 x1 = pack2(xa.z, xa.w);
            u64 x2 = pack2(xb.x, xb.y);
            u64 x3 = pack2(xb.z, xb.w);
            float4 w = *(const float4*)&Ws[(kc + k) * HID_F + tx * 4];
            u64 wb0 = pack2(w.x, w.x);
            u64 wb1 = pack2(w.y, w.y);
            u64 wb2 = pack2(w.z, w.z);
            u64 wb3 = pack2(w.w, w.w);
            fma2(acc[0][0], x0, wb0); fma2(acc[0][1], x0, wb1);
            fma2(acc[0][2], x0, wb2); fma2(acc[0][3], x0, wb3);
            fma2(acc[1][0], x1, wb0); fma2(acc[1][1], x1, wb1);
            fma2(acc[1][2], x1, wb2); fma2(acc[1][3], x1, wb3);
            fma2(acc[2][0], x2, wb0); fma2(acc[2][1], x2, wb1);
            fma2(acc[2][2], x2, wb2); fma2(acc[2][3], x2, wb3);
            fma2(acc[3][0], x3, wb0); fma2(acc[3][1], x3, wb1);
            fma2(acc[3][2], x3, wb2); fma2(acc[3][3], x3, wb3);
        }
    }
    #pragma unroll
    for (int p = 0; p < 4; ++p) {
        float2 c0 = unpack2(acc[p][0]);
        float2 c1 = unpack2(acc[p][1]);
        float2 c2 = unpack2(acc[p][2]);
        float2 c3 = unpack2(acc[p][3]);
        int ra = row0 + ty * 8 + 2 * p;
        int rb = ra + 1;
        if (ra < N) {
            __half2 h01 = __floats2half2_rn(c0.x, c1.x);
            __half2 h23 = __floats2half2_rn(c2.x, c3.x);
            *(uint2*)&g_H1h[(size_t)ra * HID_F + tx * 4] =
                make_uint2(*(unsigned*)&h01, *(unsigned*)&h23);
        }
        if (rb < N) {
            __half2 h01 = __floats2half2_rn(c0.y, c1.y);
            __half2 h23 = __floats2half2_rn(c2.y, c3.y);
            *(uint2*)&g_H1h[(size_t)rb * HID_F + tx * 4] =
                make_uint2(*(unsigned*)&h01, *(unsigned*)&h23);
        }
    }
}

// GEMM2: H2[N,32] = agg1[N,64] @ W2[64,32]; col-pair packed FFMA2 (fp32)
__global__ __launch_bounds__(256) void k_gemm2(const float* __restrict__ W, int N) {
    __shared__ float Ws[HID_F * OUT_F];
    __shared__ float xs[32 * HID_F];
    int t = threadIdx.x;
    for (int i = t; i < HID_F * OUT_F; i += 256) Ws[i] = W[i];

    int row0 = blockIdx.x * 32;
    int rows = N - row0; if (rows > 32) rows = 32;

    const float4* xg  = (const float4*)(g_agg1 + (size_t)row0 * HID_F);
    float4*       xs4 = (float4*)xs;
    const int NV = 32 * HID_F / 4;
    for (int i = t; i < NV; i += 256) {
        int r = i / (HID_F / 4);
        xs4[i] = (r < rows) ? xg[i] : make_float4(0.f, 0.f, 0.f, 0.f);
    }
    __syncthreads();

    int r = t >> 3;
    int g = (t & 7) * 4;
    if (r < rows) {
        u64 a01 = 0ull, a23 = 0ull;
        #pragma unroll 16
        for (int k = 0; k < HID_F; ++k) {
            float xv = xs[r * HID_F + k];
            u64 xp  = pack2(xv, xv);
            u64 w01 = *(const u64*)&Ws[k * OUT_F + g];
            u64 w23 = *(const u64*)&Ws[k * OUT_F + g + 2];
            fma2(a01, xp, w01);
            fma2(a23, xp, w23);
        }
        float2 f01 = unpack2(a01);
        float2 f23 = unpack2(a23);
        float* out = g_H2 + (size_t)(row0 + r) * OUT_F + g;
        *(float4*)out = make_float4(f01.x, f01.y, f23.x, f23.y);
    }
}

// ---------------------------------------------------------------------------
// Gather1: half-warp per node (2 nodes/warp), 16 lanes x 4 feats; H1 fp16
// (8B/lane/edge -> half the L2 traffic of fp32).
__global__ __launch_bounds__(256) void k_gather1(const float* __restrict__ b1, int N) {
    int w    = (blockIdx.x * blockDim.x + threadIdx.x) >> 5;
    int lane = threadIdx.x & 31;
    int h    = lane >> 4;
    int hl   = lane & 15;
    int n    = 2 * w + h;
    bool active = (n < N);
    int nn = active ? n : 0;

    float dn = g_dinv[nn];
    float c  = dn * dn;
    uint2 sh = *(const uint2*)&g_H1h[(size_t)nn * HID_F + hl * 4];
    float2 s01 = __half22float2(*(__half2*)&sh.x);
    float2 s23 = __half22float2(*(__half2*)&sh.y);
    float4 bb = *(const float4*)&b1[hl * 4];
    u64 acc0 = pack2(fmaf(s01.x, c, bb.x), fmaf(s01.y, c, bb.y));
    u64 acc1 = pack2(fmaf(s23.x, c, bb.z), fmaf(s23.y, c, bb.w));

    int start = active ? g_rowstart[nn] : 0;
    int cnt   = active ? g_deg[nn] : 0;
    int omax  = __shfl_xor_sync(0xffffffffu, cnt, 16);
    int maxcnt = cnt > omax ? cnt : omax;

    for (int base = 0; base < maxcnt; base += 16) {
        int  sl = 0; float wl = 0.f;
        if (base + hl < cnt) {
            int2 p = g_csr[start + base + hl];
            sl = p.x; wl = __int_as_float(p.y);
        }
        int remw = maxcnt - base; if (remw > 16) remw = 16;
        int remh = cnt - base;
        #pragma unroll 4
        for (int k = 0; k < remw; ++k) {
            int   sk = __shfl_sync(0xffffffffu, sl, h * 16 + k);
            float wk = __shfl_sync(0xffffffffu, wl, h * 16 + k);
            if (k < remh) {
                uint2 hv = *(const uint2*)&g_H1h[(size_t)sk * HID_F + hl * 4];
                float2 v01 = __half22float2(*(__half2*)&hv.x);
                float2 v23 = __half22float2(*(__half2*)&hv.y);
                u64 wp = pack2(wk, wk);
                fma2(acc0, wp, pack2(v01.x, v01.y));
                fma2(acc1, wp, pack2(v23.x, v23.y));
            }
        }
    }
    if (active) {
        float2 a = unpack2(acc0), b = unpack2(acc1);
        *(float4*)&g_agg1[(size_t)n * HID_F + hl * 4] =
            make_float4(fmaxf(a.x, 0.f), fmaxf(a.y, 0.f),
                        fmaxf(b.x, 0.f), fmaxf(b.y, 0.f));
    }
}

// Gather2: half-warp per node, 16 lanes x float2 (fp32), writes d_out.
// Also zeroes g_deg after its final read (self-cleaning for next replay).
__global__ __launch_bounds__(256) void k_gather2(const float* __restrict__ b2,
                                                 float* __restrict__ out, int N) {
    int w    = (blockIdx.x * blockDim.x + threadIdx.x) >> 5;
    int lane = threadIdx.x & 31;
    int h    = lane >> 4;
    int hl   = lane & 15;
    int n    = 2 * w + h;
    bool active = (n < N);
    int nn = active ? n : 0;

    float dn = g_dinv[nn];
    float c  = dn * dn;
    float2 hv = *(const float2*)&g_H2[(size_t)nn * OUT_F + hl * 2];
    float2 bb = *(const float2*)&b2[hl * 2];
    u64 acc = pack2(fmaf(hv.x, c, bb.x), fmaf(hv.y, c, bb.y));

    int start = active ? g_rowstart[nn] : 0;
    int cnt   = active ? g_deg[nn] : 0;
    int omax  = __shfl_xor_sync(0xffffffffu, cnt, 16);
    int maxcnt = cnt > omax ? cnt : omax;

    for (int base = 0; base < maxcnt; base += 16) {
        int  sl = 0; float wl = 0.f;
        if (base + hl < cnt) {
            int2 p = g_csr[start + base + hl];
            sl = p.x; wl = __int_as_float(p.y);
        }
        int remw = maxcnt - base; if (remw > 16) remw = 16;
        int remh = cnt - base;
        #pragma unroll 4
        for (int k = 0; k < remw; ++k) {
            int   sk = __shfl_sync(0xffffffffu, sl, h * 16 + k);
            float wk = __shfl_sync(0xffffffffu, wl, h * 16 + k);
            if (k < remh) {
                u64 v = *(const u64*)&g_H2[(size_t)sk * OUT_F + hl * 2];
                fma2(acc, pack2(wk, wk), v);
            }
        }
    }
    if (active) {
        float2 a = unpack2(acc);
        *(float2*)&out[(size_t)n * OUT_F + hl * 2] = a;
        if (hl == 0) g_deg[n] = 0;    // restore invariant for next launch
    }
}

// ---------------------------------------------------------------------------
extern "C" void kernel_launch(void* const* d_in, const int* in_sizes, int n_in,
                              void* d_out, int out_size) {
    const float* x  = (const float*)d_in[0];
    const int*   ei = (const int*)d_in[1];      // int32 (JAX x64 disabled)
    const float* W1 = (const float*)d_in[2];
    const float* b1 = (const float*)d_in[3];
    const float* W2 = (const float*)d_in[4];
    const float* b2 = (const float*)d_in[5];
    float*       out = (float*)d_out;

    const int N = in_sizes[0] / IN_F;     // 100000
    const int E = in_sizes[1] / 2;        // 1600000
    const int NB = (N + 255) / 256;

    const int T = 256;
    k_edge_prep<<<(E + T - 1) / T, T>>>(ei, E);     // deg starts zero
    k_scan_a<<<NB, 256>>>(N);
    k_scan_b<<<1, 512>>>(NB);
    k_gemm1  <<<(N + 127) / 128, 256>>>(x, W1, N);  // 4th launch (profiled)
    k_scan_c<<<NB, 256>>>(N);
    k_fill  <<<(E + T - 1) / T, T>>>(ei, E);

    k_gather1<<<(N + 15) / 16, 256>>>(b1, N);

    k_gemm2  <<<(N + 31) / 32, 256>>>(W2, N);
    k_gather2<<<(N + 15) / 16, 256>>>(b2, out, N);  // zeroes g_deg at end
}

// round 14
// speedup vs baseline: 1.5853x; 1.0914x over previous
#include <cuda_runtime.h>
#include <cuda_bf16.h>
#include <cuda_fp16.h>
#include <math.h>

// Problem constants (fixed by dataset): N=100000, E=1600000, dims 128->64->32
#define IN_F  128
#define HID_F 64
#define OUT_F 32
#define N_MAX 100000
#define E_MAX 1600000
#define NB_MAX 512

typedef unsigned long long u64;

// ---- packed f32x2 helpers (sm_103a FFMA2 via PTX) ----
__device__ __forceinline__ u64 pack2(float lo, float hi) {
    u64 r; asm("mov.b64 %0, {%1, %2};" : "=l"(r) : "f"(lo), "f"(hi)); return r;
}
__device__ __forceinline__ void fma2(u64& d, u64 a, u64 b) {
    asm("fma.rn.f32x2 %0, %1, %2, %0;" : "+l"(d) : "l"(a), "l"(b));
}
__device__ __forceinline__ float2 unpack2(u64 v) {
    float2 f; asm("mov.b64 {%0, %1}, %2;" : "=f"(f.x), "=f"(f.y) : "l"(v)); return f;
}

// ---- device scratch (no cudaMalloc allowed) ----
// g_deg starts zero (static init) and is re-zeroed by gather2 (last reader).
__device__ int    g_deg    [N_MAX];                 // in-degree (self-loop excluded)
__device__ float  g_dinv   [N_MAX];
__device__ int    g_rowstart[N_MAX];
__device__ int    g_cursor [N_MAX];
__device__ int    g_bsum   [NB_MAX];
__device__ int    g_bofs   [NB_MAX];
__device__ int2   g_csr    [E_MAX];                 // packed (src, w)
__device__ __half g_H1h [(size_t)N_MAX * HID_F];    // x @ W1 (fp16)
__device__ float  g_agg1[(size_t)N_MAX * HID_F];    // relu(agg), fp32
__device__ __half g_H2h [(size_t)N_MAX * OUT_F];    // layer-2 transform (fp16)

// ---------------------------------------------------------------------------
__global__ void k_edge_prep(const int* __restrict__ ei, int E) {
    int e = blockIdx.x * blockDim.x + threadIdx.x;
    if (e < E) atomicAdd(&g_deg[ei[E + e]], 1);
}

// SA: per-block indegree sums + dinv (deg = indeg + 1 self-loop)
__global__ __launch_bounds__(256) void k_scan_a(int N) {
    __shared__ int sh[256];
    int t = threadIdx.x;
    int n = blockIdx.x * 256 + t;
    int cnt = (n < N) ? g_deg[n] : 0;
    if (n < N) g_dinv[n] = rsqrtf((float)(cnt + 1));
    sh[t] = cnt;
    __syncthreads();
    for (int off = 128; off > 0; off >>= 1) {
        if (t < off) sh[t] += sh[t + off];
        __syncthreads();
    }
    if (t == 0) g_bsum[blockIdx.x] = sh[0];
}

__global__ __launch_bounds__(512) void k_scan_b(int NB) {
    __shared__ int sh[512];
    int t = threadIdx.x;
    int v = (t < NB) ? g_bsum[t] : 0;
    sh[t] = v;
    __syncthreads();
    for (int off = 1; off < 512; off <<= 1) {
        int add = (t >= off) ? sh[t - off] : 0;
        __syncthreads();
        sh[t] += add;
        __syncthreads();
    }
    if (t < NB) g_bofs[t] = sh[t] - v;
}

__global__ __launch_bounds__(256) void k_scan_c(int N) {
    __shared__ int sh[256];
    int t = threadIdx.x;
    int n = blockIdx.x * 256 + t;
    int v = (n < N) ? g_deg[n] : 0;
    sh[t] = v;
    __syncthreads();
    for (int off = 1; off < 256; off <<= 1) {
        int add = (t >= off) ? sh[t - off] : 0;
        __syncthreads();
        sh[t] += add;
        __syncthreads();
    }
    if (n < N) {
        int excl = sh[t] - v + g_bofs[blockIdx.x];
        g_rowstart[n] = excl;
        g_cursor[n]   = excl;
    }
}

__global__ void k_fill(const int* __restrict__ ei, int E) {
    int e = blockIdx.x * blockDim.x + threadIdx.x;
    if (e < E) {
        int s = ei[e];
        int d = ei[E + e];
        int pos = atomicAdd(&g_cursor[d], 1);
        g_csr[pos] = make_int2(s, __float_as_int(g_dinv[s] * g_dinv[d]));
    }
}

// ---------------------------------------------------------------------------
// GEMM1 (R8-proven FFMA2 version): 128x64 block, 8x4 micro-tile, row-pair
// packed accumulators; fp16 output store.
#define KC 32
#define XT_STRIDE 132
__global__ __launch_bounds__(256) void k_gemm1(const float* __restrict__ x,
                                               const float* __restrict__ W,
                                               int N) {
    __shared__ float Ws[IN_F * HID_F];      // 32 KB
    __shared__ float xsT[KC * XT_STRIDE];   // ~16.5 KB
    int t  = threadIdx.x;
    int ty = t >> 4;
    int tx = t & 15;
    int row0 = blockIdx.x * 128;

    for (int i = t; i < IN_F * HID_F / 4; i += 256)
        ((float4*)Ws)[i] = ((const float4*)W)[i];

    u64 acc[4][4];
    #pragma unroll
    for (int p = 0; p < 4; ++p)
        #pragma unroll
        for (int c = 0; c < 4; ++c) acc[p][c] = 0ull;

    for (int kc = 0; kc < IN_F; kc += KC) {
        __syncthreads();
        for (int i = t; i < 128 * (KC / 4); i += 256) {
            int r  = i >> 3;
            int kq = i & 7;
            int row = row0 + r;
            float4 v = make_float4(0.f, 0.f, 0.f, 0.f);
            if (row < N) v = *(const float4*)&x[(size_t)row * IN_F + kc + kq * 4];
            xsT[(kq * 4 + 0) * XT_STRIDE + r] = v.x;
            xsT[(kq * 4 + 1) * XT_STRIDE + r] = v.y;
            xsT[(kq * 4 + 2) * XT_STRIDE + r] = v.z;
            xsT[(kq * 4 + 3) * XT_STRIDE + r] = v.w;
        }
        __syncthreads();
        #pragma unroll
        for (int k = 0; k < KC; ++k) {
            const float* xrow = &xsT[k * XT_STRIDE + ty * 8];
            float4 xa = *(const float4*)&xrow[0];
            float4 xb = *(const float4*)&xrow[4];
            u64 x0 = pack2(xa.x, xa.y);
            u64 x1 = pack2(xa.z, xa.w);
            u64 x2 = pack2(xb.x, xb.y);
            u64 x3 = pack2(xb.z, xb.w);
            float4 w = *(const float4*)&Ws[(kc + k) * HID_F + tx * 4];
            u64 wb0 = pack2(w.x, w.x);
            u64 wb1 = pack2(w.y, w.y);
            u64 wb2 = pack2(w.z, w.z);
            u64 wb3 = pack2(w.w, w.w);
            fma2(acc[0][0], x0, wb0); fma2(acc[0][1], x0, wb1);
            fma2(acc[0][2], x0, wb2); fma2(acc[0][3], x0, wb3);
            fma2(acc[1][0], x1, wb0); fma2(acc[1][1], x1, wb1);
            fma2(acc[1][2], x1, wb2); fma2(acc[1][3], x1, wb3);
            fma2(acc[2][0], x2, wb0); fma2(acc[2][1], x2, wb1);
            fma2(acc[2][2], x2, wb2); fma2(acc[2][3], x2, wb3);
            fma2(acc[3][0], x3, wb0); fma2(acc[3][1], x3, wb1);
            fma2(acc[3][2], x3, wb2); fma2(acc[3][3], x3, wb3);
        }
    }
    #pragma unroll
    for (int p = 0; p < 4; ++p) {
        float2 c0 = unpack2(acc[p][0]);
        float2 c1 = unpack2(acc[p][1]);
        float2 c2 = unpack2(acc[p][2]);
        float2 c3 = unpack2(acc[p][3]);
        int ra = row0 + ty * 8 + 2 * p;
        int rb = ra + 1;
        if (ra < N) {
            __half2 h01 = __floats2half2_rn(c0.x, c1.x);
            __half2 h23 = __floats2half2_rn(c2.x, c3.x);
            *(uint2*)&g_H1h[(size_t)ra * HID_F + tx * 4] =
                make_uint2(*(unsigned*)&h01, *(unsigned*)&h23);
        }
        if (rb < N) {
            __half2 h01 = __floats2half2_rn(c0.y, c1.y);
            __half2 h23 = __floats2half2_rn(c2.y, c3.y);
            *(uint2*)&g_H1h[(size_t)rb * HID_F + tx * 4] =
                make_uint2(*(unsigned*)&h01, *(unsigned*)&h23);
        }
    }
}

// GEMM2: H2[N,32] = agg1[N,64] @ W2[64,32]; fp32 math, fp16 store
__global__ __launch_bounds__(256) void k_gemm2(const float* __restrict__ W, int N) {
    __shared__ float Ws[HID_F * OUT_F];
    __shared__ float xs[32 * HID_F];
    int t = threadIdx.x;
    for (int i = t; i < HID_F * OUT_F; i += 256) Ws[i] = W[i];

    int row0 = blockIdx.x * 32;
    int rows = N - row0; if (rows > 32) rows = 32;

    const float4* xg  = (const float4*)(g_agg1 + (size_t)row0 * HID_F);
    float4*       xs4 = (float4*)xs;
    const int NV = 32 * HID_F / 4;
    for (int i = t; i < NV; i += 256) {
        int r = i / (HID_F / 4);
        xs4[i] = (r < rows) ? xg[i] : make_float4(0.f, 0.f, 0.f, 0.f);
    }
    __syncthreads();

    int r = t >> 3;
    int g = (t & 7) * 4;
    if (r < rows) {
        u64 a01 = 0ull, a23 = 0ull;
        #pragma unroll 16
        for (int k = 0; k < HID_F; ++k) {
            float xv = xs[r * HID_F + k];
            u64 xp  = pack2(xv, xv);
            u64 w01 = *(const u64*)&Ws[k * OUT_F + g];
            u64 w23 = *(const u64*)&Ws[k * OUT_F + g + 2];
            fma2(a01, xp, w01);
            fma2(a23, xp, w23);
        }
        float2 f01 = unpack2(a01);
        float2 f23 = unpack2(a23);
        __half2 h01 = __floats2half2_rn(f01.x, f01.y);
        __half2 h23 = __floats2half2_rn(f23.x, f23.y);
        *(uint2*)&g_H2h[(size_t)(row0 + r) * OUT_F + g] =
            make_uint2(*(unsigned*)&h01, *(unsigned*)&h23);
    }
}

// ---------------------------------------------------------------------------
// Gather1: QUARTER-warp per node (4 nodes/warp). 8 lanes x 8 fp16 feats
// (uint4 = 16B/lane/edge, one LDG.128 per edge; 4 edges per warp-iteration).
__global__ __launch_bounds__(256) void k_gather1(const float* __restrict__ b1, int N) {
    int w    = (blockIdx.x * blockDim.x + threadIdx.x) >> 5;
    int lane = threadIdx.x & 31;
    int h    = lane >> 3;          // quarter id 0..3
    int hl   = lane & 7;           // lane within quarter
    int n    = 4 * w + h;
    bool active = (n < N);
    int nn = active ? n : 0;

    float dn = g_dinv[nn];
    float c  = dn * dn;
    uint4 sh = *(const uint4*)&g_H1h[(size_t)nn * HID_F + hl * 8];
    float2 s0 = __half22float2(*(__half2*)&sh.x);
    float2 s1 = __half22float2(*(__half2*)&sh.y);
    float2 s2 = __half22float2(*(__half2*)&sh.z);
    float2 s3 = __half22float2(*(__half2*)&sh.w);
    float4 ba = *(const float4*)&b1[hl * 8];
    float4 bc = *(const float4*)&b1[hl * 8 + 4];
    u64 acc0 = pack2(fmaf(s0.x, c, ba.x), fmaf(s0.y, c, ba.y));
    u64 acc1 = pack2(fmaf(s1.x, c, ba.z), fmaf(s1.y, c, ba.w));
    u64 acc2 = pack2(fmaf(s2.x, c, bc.x), fmaf(s2.y, c, bc.y));
    u64 acc3 = pack2(fmaf(s3.x, c, bc.z), fmaf(s3.y, c, bc.w));

    int start = active ? g_rowstart[nn] : 0;
    int cnt   = active ? g_deg[nn] : 0;
    int m = cnt;
    m = max(m, __shfl_xor_sync(0xffffffffu, m, 8));
    m = max(m, __shfl_xor_sync(0xffffffffu, m, 16));   // warp-uniform max

    for (int base = 0; base < m; base += 8) {
        int  sl = 0; float wl = 0.f;
        if (base + hl < cnt) {
            int2 p = g_csr[start + base + hl];
            sl = p.x; wl = __int_as_float(p.y);
        }
        int remw = m - base; if (remw > 8) remw = 8;   // warp-uniform
        int remh = cnt - base;                          // per-quarter
        #pragma unroll 4
        for (int k = 0; k < remw; ++k) {
            int   sk = __shfl_sync(0xffffffffu, sl, h * 8 + k);
            float wk = __shfl_sync(0xffffffffu, wl, h * 8 + k);
            if (k < remh) {
                uint4 hv = *(const uint4*)&g_H1h[(size_t)sk * HID_F + hl * 8];
                float2 v0 = __half22float2(*(__half2*)&hv.x);
                float2 v1 = __half22float2(*(__half2*)&hv.y);
                float2 v2 = __half22float2(*(__half2*)&hv.z);
                float2 v3 = __half22float2(*(__half2*)&hv.w);
                u64 wp = pack2(wk, wk);
                fma2(acc0, wp, pack2(v0.x, v0.y));
                fma2(acc1, wp, pack2(v1.x, v1.y));
                fma2(acc2, wp, pack2(v2.x, v2.y));
                fma2(acc3, wp, pack2(v3.x, v3.y));
            }
        }
    }
    if (active) {
        float2 a0 = unpack2(acc0), a1 = unpack2(acc1);
        float2 a2 = unpack2(acc2), a3 = unpack2(acc3);
        *(float4*)&g_agg1[(size_t)n * HID_F + hl * 8] =
            make_float4(fmaxf(a0.x, 0.f), fmaxf(a0.y, 0.f),
                        fmaxf(a1.x, 0.f), fmaxf(a1.y, 0.f));
        *(float4*)&g_agg1[(size_t)n * HID_F + hl * 8 + 4] =
            make_float4(fmaxf(a2.x, 0.f), fmaxf(a2.y, 0.f),
                        fmaxf(a3.x, 0.f), fmaxf(a3.y, 0.f));
    }
}

// Gather2: quarter-warp per node, 8 lanes x 4 fp16 feats (uint2 = 8B/lane),
// fp32 accumulate, writes d_out; zeroes g_deg (self-cleaning).
__global__ __launch_bounds__(256) void k_gather2(const float* __restrict__ b2,
                                                 float* __restrict__ out, int N) {
    int w    = (blockIdx.x * blockDim.x + threadIdx.x) >> 5;
    int lane = threadIdx.x & 31;
    int h    = lane >> 3;
    int hl   = lane & 7;
    int n    = 4 * w + h;
    bool active = (n < N);
    int nn = active ? n : 0;

    float dn = g_dinv[nn];
    float c  = dn * dn;
    uint2 sh = *(const uint2*)&g_H2h[(size_t)nn * OUT_F + hl * 4];
    float2 s0 = __half22float2(*(__half2*)&sh.x);
    float2 s1 = __half22float2(*(__half2*)&sh.y);
    float4 bb = *(const float4*)&b2[hl * 4];
    u64 acc0 = pack2(fmaf(s0.x, c, bb.x), fmaf(s0.y, c, bb.y));
    u64 acc1 = pack2(fmaf(s1.x, c, bb.z), fmaf(s1.y, c, bb.w));

    int start = active ? g_rowstart[nn] : 0;
    int cnt   = active ? g_deg[nn] : 0;
    int m = cnt;
    m = max(m, __shfl_xor_sync(0xffffffffu, m, 8));
    m = max(m, __shfl_xor_sync(0xffffffffu, m, 16));

    for (int base = 0; base < m; base += 8) {
        int  sl = 0; float wl = 0.f;
        if (base + hl < cnt) {
            int2 p = g_csr[start + base + hl];
            sl = p.x; wl = __int_as_float(p.y);
        }
        int remw = m - base; if (remw > 8) remw = 8;
        int remh = cnt - base;
        #pragma unroll 4
        for (int k = 0; k < remw; ++k) {
            int   sk = __shfl_sync(0xffffffffu, sl, h * 8 + k);
            float wk = __shfl_sync(0xffffffffu, wl, h * 8 + k);
            if (k < remh) {
                uint2 hv = *(const uint2*)&g_H2h[(size_t)sk * OUT_F + hl * 4];
                float2 v0 = __half22float2(*(__half2*)&hv.x);
                float2 v1 = __half22float2(*(__half2*)&hv.y);
                u64 wp = pack2(wk, wk);
                fma2(acc0, wp, pack2(v0.x, v0.y));
                fma2(acc1, wp, pack2(v1.x, v1.y));
            }
        }
    }
    if (active) {
        float2 a0 = unpack2(acc0), a1 = unpack2(acc1);
        *(float4*)&out[(size_t)n * OUT_F + hl * 4] =
            make_float4(a0.x, a0.y, a1.x, a1.y);
        if (hl == 0) g_deg[n] = 0;    // restore invariant for next launch
    }
}

// ---------------------------------------------------------------------------
extern "C" void kernel_launch(void* const* d_in, const int* in_sizes, int n_in,
                              void* d_out, int out_size) {
    const float* x  = (const float*)d_in[0];
    const int*   ei = (const int*)d_in[1];      // int32 (JAX x64 disabled)
    const float* W1 = (const float*)d_in[2];
    const float* b1 = (const float*)d_in[3];
    const float* W2 = (const float*)d_in[4];
    const float* b2 = (const float*)d_in[5];
    float*       out = (float*)d_out;

    const int N = in_sizes[0] / IN_F;     // 100000
    const int E = in_sizes[1] / 2;        // 1600000
    const int NB = (N + 255) / 256;

    const int T = 256;
    k_edge_prep<<<(E + T - 1) / T, T>>>(ei, E);     // deg starts zero
    k_scan_a<<<NB, 256>>>(N);
    k_scan_b<<<1, 512>>>(NB);
    k_gemm1  <<<(N + 127) / 128, 256>>>(x, W1, N);  // 4th launch (profiled)
    k_scan_c<<<NB, 256>>>(N);
    k_fill  <<<(E + T - 1) / T, T>>>(ei, E);

    // 32 nodes per 256-thread block (4 per warp)
    k_gather1<<<(N + 31) / 32, 256>>>(b1, N);

    k_gemm2  <<<(N + 31) / 32, 256>>>(W2, N);
    k_gather2<<<(N + 31) / 32, 256>>>(b2, out, N);  // zeroes g_deg at end
}

// round 15
// speedup vs baseline: 1.6586x; 1.0462x over previous
#include <cuda_runtime.h>
#include <cuda_bf16.h>
#include <cuda_fp16.h>
#include <math.h>

// Problem constants (fixed by dataset): N=100000, E=1600000, dims 128->64->32
#define IN_F  128
#define HID_F 64
#define OUT_F 32
#define N_MAX 100000
#define E_MAX 1600000
#define NB_MAX 512

typedef unsigned long long u64;

// ---- packed f32x2 helpers (sm_103a FFMA2/FADD2 via PTX) ----
__device__ __forceinline__ u64 pack2(float lo, float hi) {
    u64 r; asm("mov.b64 %0, {%1, %2};" : "=l"(r) : "f"(lo), "f"(hi)); return r;
}
__device__ __forceinline__ void fma2(u64& d, u64 a, u64 b) {
    asm("fma.rn.f32x2 %0, %1, %2, %0;" : "+l"(d) : "l"(a), "l"(b));
}
__device__ __forceinline__ void add2(u64& d, u64 a) {
    asm("add.rn.f32x2 %0, %0, %1;" : "+l"(d) : "l"(a));
}
__device__ __forceinline__ float2 unpack2(u64 v) {
    float2 f; asm("mov.b64 {%0, %1}, %2;" : "=f"(f.x), "=f"(f.y) : "l"(v)); return f;
}

// ---- device scratch (no cudaMalloc allowed) ----
// g_deg starts zero (static init) and is re-zeroed by gather2 (last reader).
__device__ int    g_deg    [N_MAX];                 // in-degree (self-loop excluded)
__device__ float  g_dinv   [N_MAX];
__device__ int    g_rowstart[N_MAX];
__device__ int    g_cursor [N_MAX];
__device__ int    g_bsum   [NB_MAX];
__device__ int    g_bofs   [NB_MAX];
__device__ int    g_csr    [E_MAX];                 // src index only (dinv folded into features)
__device__ __half g_H1h [(size_t)N_MAX * HID_F];    // dinv[n] * (x @ W1)[n]  (fp16)
__device__ float  g_agg1[(size_t)N_MAX * HID_F];    // relu(agg), fp32
__device__ __half g_H2h [(size_t)N_MAX * OUT_F];    // dinv[n] * (agg1 @ W2)[n] (fp16)

// ---------------------------------------------------------------------------
__global__ void k_edge_prep(const int* __restrict__ ei, int E) {
    int e = blockIdx.x * blockDim.x + threadIdx.x;
    if (e < E) atomicAdd(&g_deg[ei[E + e]], 1);
}

// SA: per-block indegree sums + dinv (deg = indeg + 1 self-loop)
__global__ __launch_bounds__(256) void k_scan_a(int N) {
    __shared__ int sh[256];
    int t = threadIdx.x;
    int n = blockIdx.x * 256 + t;
    int cnt = (n < N) ? g_deg[n] : 0;
    if (n < N) g_dinv[n] = rsqrtf((float)(cnt + 1));
    sh[t] = cnt;
    __syncthreads();
    for (int off = 128; off > 0; off >>= 1) {
        if (t < off) sh[t] += sh[t + off];
        __syncthreads();
    }
    if (t == 0) g_bsum[blockIdx.x] = sh[0];
}

__global__ __launch_bounds__(512) void k_scan_b(int NB) {
    __shared__ int sh[512];
    int t = threadIdx.x;
    int v = (t < NB) ? g_bsum[t] : 0;
    sh[t] = v;
    __syncthreads();
    for (int off = 1; off < 512; off <<= 1) {
        int add = (t >= off) ? sh[t - off] : 0;
        __syncthreads();
        sh[t] += add;
        __syncthreads();
    }
    if (t < NB) g_bofs[t] = sh[t] - v;
}

__global__ __launch_bounds__(256) void k_scan_c(int N) {
    __shared__ int sh[256];
    int t = threadIdx.x;
    int n = blockIdx.x * 256 + t;
    int v = (n < N) ? g_deg[n] : 0;
    sh[t] = v;
    __syncthreads();
    for (int off = 1; off < 256; off <<= 1) {
        int add = (t >= off) ? sh[t - off] : 0;
        __syncthreads();
        sh[t] += add;
        __syncthreads();
    }
    if (n < N) {
        int excl = sh[t] - v + g_bofs[blockIdx.x];
        g_rowstart[n] = excl;
        g_cursor[n]   = excl;
    }
}

// Fill CSR: src index only — no dinv gather, 4B random store
__global__ void k_fill(const int* __restrict__ ei, int E) {
    int e = blockIdx.x * blockDim.x + threadIdx.x;
    if (e < E) {
        int s = ei[e];
        int d = ei[E + e];
        int pos = atomicAdd(&g_cursor[d], 1);
        g_csr[pos] = s;
    }
}

// ---------------------------------------------------------------------------
// GEMM1 (R8-proven FFMA2): 128x64 block, 8x4 micro-tile, row-pair packed
// accumulators; stores dinv[row]-scaled fp16.
#define KC 32
#define XT_STRIDE 132
__global__ __launch_bounds__(256) void k_gemm1(const float* __restrict__ x,
                                               const float* __restrict__ W,
                                               int N) {
    __shared__ float Ws[IN_F * HID_F];      // 32 KB
    __shared__ float xsT[KC * XT_STRIDE];   // ~16.5 KB
    int t  = threadIdx.x;
    int ty = t >> 4;
    int tx = t & 15;
    int row0 = blockIdx.x * 128;

    for (int i = t; i < IN_F * HID_F / 4; i += 256)
        ((float4*)Ws)[i] = ((const float4*)W)[i];

    u64 acc[4][4];
    #pragma unroll
    for (int p = 0; p < 4; ++p)
        #pragma unroll
        for (int c = 0; c < 4; ++c) acc[p][c] = 0ull;

    for (int kc = 0; kc < IN_F; kc += KC) {
        __syncthreads();
        for (int i = t; i < 128 * (KC / 4); i += 256) {
            int r  = i >> 3;
            int kq = i & 7;
            int row = row0 + r;
            float4 v = make_float4(0.f, 0.f, 0.f, 0.f);
            if (row < N) v = *(const float4*)&x[(size_t)row * IN_F + kc + kq * 4];
            xsT[(kq * 4 + 0) * XT_STRIDE + r] = v.x;
            xsT[(kq * 4 + 1) * XT_STRIDE + r] = v.y;
            xsT[(kq * 4 + 2) * XT_STRIDE + r] = v.z;
            xsT[(kq * 4 + 3) * XT_STRIDE + r] = v.w;
        }
        __syncthreads();
        #pragma unroll
        for (int k = 0; k < KC; ++k) {
            const float* xrow = &xsT[k * XT_STRIDE + ty * 8];
            float4 xa = *(const float4*)&xrow[0];
            float4 xb = *(const float4*)&xrow[4];
            u64 x0 = pack2(xa.x, xa.y);
            u64 x1 = pack2(xa.z, xa.w);
            u64 x2 = pack2(xb.x, xb.y);
            u64 x3 = pack2(xb.z, xb.w);
            float4 w = *(const float4*)&Ws[(kc + k) * HID_F + tx * 4];
            u64 wb0 = pack2(w.x, w.x);
            u64 wb1 = pack2(w.y, w.y);
            u64 wb2 = pack2(w.z, w.z);
            u64 wb3 = pack2(w.w, w.w);
            fma2(acc[0][0], x0, wb0); fma2(acc[0][1], x0, wb1);
            fma2(acc[0][2], x0, wb2); fma2(acc[0][3], x0, wb3);
            fma2(acc[1][0], x1, wb0); fma2(acc[1][1], x1, wb1);
            fma2(acc[1][2], x1, wb2); fma2(acc[1][3], x1, wb3);
            fma2(acc[2][0], x2, wb0); fma2(acc[2][1], x2, wb1);
            fma2(acc[2][2], x2, wb2); fma2(acc[2][3], x2, wb3);
            fma2(acc[3][0], x3, wb0); fma2(acc[3][1], x3, wb1);
            fma2(acc[3][2], x3, wb2); fma2(acc[3][3], x3, wb3);
        }
    }
    #pragma unroll
    for (int p = 0; p < 4; ++p) {
        float2 c0 = unpack2(acc[p][0]);
        float2 c1 = unpack2(acc[p][1]);
        float2 c2 = unpack2(acc[p][2]);
        float2 c3 = unpack2(acc[p][3]);
        int ra = row0 + ty * 8 + 2 * p;
        int rb = ra + 1;
        if (ra < N) {
            float dv = g_dinv[ra];
            __half2 h01 = __floats2half2_rn(dv * c0.x, dv * c1.x);
            __half2 h23 = __floats2half2_rn(dv * c2.x, dv * c3.x);
            *(uint2*)&g_H1h[(size_t)ra * HID_F + tx * 4] =
                make_uint2(*(unsigned*)&h01, *(unsigned*)&h23);
        }
        if (rb < N) {
            float dv = g_dinv[rb];
            __half2 h01 = __floats2half2_rn(dv * c0.y, dv * c1.y);
            __half2 h23 = __floats2half2_rn(dv * c2.y, dv * c3.y);
            *(uint2*)&g_H1h[(size_t)rb * HID_F + tx * 4] =
                make_uint2(*(unsigned*)&h01, *(unsigned*)&h23);
        }
    }
}

// GEMM2: H2pre[N,32] = dinv * (agg1[N,64] @ W2[64,32]); fp32 math, fp16 store
__global__ __launch_bounds__(256) void k_gemm2(const float* __restrict__ W, int N) {
    __shared__ float Ws[HID_F * OUT_F];
    __shared__ float xs[32 * HID_F];
    int t = threadIdx.x;
    for (int i = t; i < HID_F * OUT_F; i += 256) Ws[i] = W[i];

    int row0 = blockIdx.x * 32;
    int rows = N - row0; if (rows > 32) rows = 32;

    const float4* xg  = (const float4*)(g_agg1 + (size_t)row0 * HID_F);
    float4*       xs4 = (float4*)xs;
    const int NV = 32 * HID_F / 4;
    for (int i = t; i < NV; i += 256) {
        int r = i / (HID_F / 4);
        xs4[i] = (r < rows) ? xg[i] : make_float4(0.f, 0.f, 0.f, 0.f);
    }
    __syncthreads();

    int r = t >> 3;
    int g = (t & 7) * 4;
    if (r < rows) {
        u64 a01 = 0ull, a23 = 0ull;
        #pragma unroll 16
        for (int k = 0; k < HID_F; ++k) {
            float xv = xs[r * HID_F + k];
            u64 xp  = pack2(xv, xv);
            u64 w01 = *(const u64*)&Ws[k * OUT_F + g];
            u64 w23 = *(const u64*)&Ws[k * OUT_F + g + 2];
            fma2(a01, xp, w01);
            fma2(a23, xp, w23);
        }
        float2 f01 = unpack2(a01);
        float2 f23 = unpack2(a23);
        float dv = g_dinv[row0 + r];
        __half2 h01 = __floats2half2_rn(dv * f01.x, dv * f01.y);
        __half2 h23 = __floats2half2_rn(dv * f23.x, dv * f23.y);
        *(uint2*)&g_H2h[(size_t)(row0 + r) * OUT_F + g] =
            make_uint2(*(unsigned*)&h01, *(unsigned*)&h23);
    }
}

// ---------------------------------------------------------------------------
// Gather1: quarter-warp per node (4 nodes/warp), 8 lanes x 8 fp16 feats.
// Weightless inner loop: 1 shfl + 1 LDG.128 + cvt + add2 per edge.
// Epilogue: relu(dinv[n]*acc + b1).
__global__ __launch_bounds__(256) void k_gather1(const float* __restrict__ b1, int N) {
    int w    = (blockIdx.x * blockDim.x + threadIdx.x) >> 5;
    int lane = threadIdx.x & 31;
    int h    = lane >> 3;          // quarter id 0..3
    int hl   = lane & 7;           // lane within quarter
    int n    = 4 * w + h;
    bool active = (n < N);
    int nn = active ? n : 0;

    // self term: H1pre[n] (already dinv[n]-scaled)
    uint4 sh = *(const uint4*)&g_H1h[(size_t)nn * HID_F + hl * 8];
    float2 s0 = __half22float2(*(__half2*)&sh.x);
    float2 s1 = __half22float2(*(__half2*)&sh.y);
    float2 s2 = __half22float2(*(__half2*)&sh.z);
    float2 s3 = __half22float2(*(__half2*)&sh.w);
    u64 acc0 = pack2(s0.x, s0.y);
    u64 acc1 = pack2(s1.x, s1.y);
    u64 acc2 = pack2(s2.x, s2.y);
    u64 acc3 = pack2(s3.x, s3.y);

    int start = active ? g_rowstart[nn] : 0;
    int cnt   = active ? g_deg[nn] : 0;
    int m = cnt;
    m = max(m, __shfl_xor_sync(0xffffffffu, m, 8));
    m = max(m, __shfl_xor_sync(0xffffffffu, m, 16));   // warp-uniform max

    for (int base = 0; base < m; base += 8) {
        int sl = 0;
        if (base + hl < cnt) sl = g_csr[start + base + hl];
        int remw = m - base; if (remw > 8) remw = 8;   // warp-uniform
        int remh = cnt - base;                          // per-quarter
        #pragma unroll 4
        for (int k = 0; k < remw; ++k) {
            int sk = __shfl_sync(0xffffffffu, sl, h * 8 + k);
            if (k < remh) {
                uint4 hv = *(const uint4*)&g_H1h[(size_t)sk * HID_F + hl * 8];
                float2 v0 = __half22float2(*(__half2*)&hv.x);
                float2 v1 = __half22float2(*(__half2*)&hv.y);
                float2 v2 = __half22float2(*(__half2*)&hv.z);
                float2 v3 = __half22float2(*(__half2*)&hv.w);
                add2(acc0, pack2(v0.x, v0.y));
                add2(acc1, pack2(v1.x, v1.y));
                add2(acc2, pack2(v2.x, v2.y));
                add2(acc3, pack2(v3.x, v3.y));
            }
        }
    }
    if (active) {
        float dn = g_dinv[n];
        float4 ba = *(const float4*)&b1[hl * 8];
        float4 bc = *(const float4*)&b1[hl * 8 + 4];
        float2 a0 = unpack2(acc0), a1 = unpack2(acc1);
        float2 a2 = unpack2(acc2), a3 = unpack2(acc3);
        *(float4*)&g_agg1[(size_t)n * HID_F + hl * 8] =
            make_float4(fmaxf(fmaf(dn, a0.x, ba.x), 0.f),
                        fmaxf(fmaf(dn, a0.y, ba.y), 0.f),
                        fmaxf(fmaf(dn, a1.x, ba.z), 0.f),
                        fmaxf(fmaf(dn, a1.y, ba.w), 0.f));
        *(float4*)&g_agg1[(size_t)n * HID_F + hl * 8 + 4] =
            make_float4(fmaxf(fmaf(dn, a2.x, bc.x), 0.f),
                        fmaxf(fmaf(dn, a2.y, bc.y), 0.f),
                        fmaxf(fmaf(dn, a3.x, bc.z), 0.f),
                        fmaxf(fmaf(dn, a3.y, bc.w), 0.f));
    }
}

// Gather2: quarter-warp per node, 8 lanes x 4 fp16 feats, weightless loop,
// writes d_out = dinv[n]*acc + b2; zeroes g_deg (self-cleaning).
__global__ __launch_bounds__(256) void k_gather2(const float* __restrict__ b2,
                                                 float* __restrict__ out, int N) {
    int w    = (blockIdx.x * blockDim.x + threadIdx.x) >> 5;
    int lane = threadIdx.x & 31;
    int h    = lane >> 3;
    int hl   = lane & 7;
    int n    = 4 * w + h;
    bool active = (n < N);
    int nn = active ? n : 0;

    uint2 sh = *(const uint2*)&g_H2h[(size_t)nn * OUT_F + hl * 4];
    float2 s0 = __half22float2(*(__half2*)&sh.x);
    float2 s1 = __half22float2(*(__half2*)&sh.y);
    u64 acc0 = pack2(s0.x, s0.y);
    u64 acc1 = pack2(s1.x, s1.y);

    int start = active ? g_rowstart[nn] : 0;
    int cnt   = active ? g_deg[nn] : 0;
    int m = cnt;
    m = max(m, __shfl_xor_sync(0xffffffffu, m, 8));
    m = max(m, __shfl_xor_sync(0xffffffffu, m, 16));

    for (int base = 0; base < m; base += 8) {
        int sl = 0;
        if (base + hl < cnt) sl = g_csr[start + base + hl];
        int remw = m - base; if (remw > 8) remw = 8;
        int remh = cnt - base;
        #pragma unroll 4
        for (int k = 0; k < remw; ++k) {
            int sk = __shfl_sync(0xffffffffu, sl, h * 8 + k);
            if (k < remh) {
                uint2 hv = *(const uint2*)&g_H2h[(size_t)sk * OUT_F + hl * 4];
                float2 v0 = __half22float2(*(__half2*)&hv.x);
                float2 v1 = __half22float2(*(__half2*)&hv.y);
                add2(acc0, pack2(v0.x, v0.y));
                add2(acc1, pack2(v1.x, v1.y));
            }
        }
    }
    if (active) {
        float dn = g_dinv[n];
        float4 bb = *(const float4*)&b2[hl * 4];
        float2 a0 = unpack2(acc0), a1 = unpack2(acc1);
        *(float4*)&out[(size_t)n * OUT_F + hl * 4] =
            make_float4(fmaf(dn, a0.x, bb.x), fmaf(dn, a0.y, bb.y),
                        fmaf(dn, a1.x, bb.z), fmaf(dn, a1.y, bb.w));
        if (hl == 0) g_deg[n] = 0;    // restore invariant for next launch
    }
}

// ---------------------------------------------------------------------------
extern "C" void kernel_launch(void* const* d_in, const int* in_sizes, int n_in,
                              void* d_out, int out_size) {
    const float* x  = (const float*)d_in[0];
    const int*   ei = (const int*)d_in[1];      // int32 (JAX x64 disabled)
    const float* W1 = (const float*)d_in[2];
    const float* b1 = (const float*)d_in[3];
    const float* W2 = (const float*)d_in[4];
    const float* b2 = (const float*)d_in[5];
    float*       out = (float*)d_out;

    const int N = in_sizes[0] / IN_F;     // 100000
    const int E = in_sizes[1] / 2;        // 1600000
    const int NB = (N + 255) / 256;

    const int T = 256;
    k_edge_prep<<<(E + T - 1) / T, T>>>(ei, E);     // deg starts zero
    k_scan_a<<<NB, 256>>>(N);                       // computes dinv
    k_scan_b<<<1, 512>>>(NB);
    k_gemm1  <<<(N + 127) / 128, 256>>>(x, W1, N);  // 4th launch (profiled; needs dinv)
    k_scan_c<<<NB, 256>>>(N);
    k_fill  <<<(E + T - 1) / T, T>>>(ei, E);

    k_gather1<<<(N + 31) / 32, 256>>>(b1, N);

    k_gemm2  <<<(N + 31) / 32, 256>>>(W2, N);
    k_gather2<<<(N + 31) / 32, 256>>>(b2, out, N);  // zeroes g_deg at end
}

// round 16
// speedup vs baseline: 1.8576x; 1.1200x over previous
#include <cuda_runtime.h>
#include <cuda_bf16.h>
#include <cuda_fp16.h>
#include <math.h>

// Problem constants (fixed by dataset): N=100000, E=1600000, dims 128->64->32
#define IN_F  128
#define HID_F 64
#define OUT_F 32
#define N_MAX 100000
#define E_MAX 1600000
#define NB_MAX 512

typedef unsigned long long u64;
typedef unsigned int u32;

// ---- packed f32x2 helpers (sm_103a FFMA2/FADD2 via PTX) ----
__device__ __forceinline__ u64 pack2(float lo, float hi) {
    u64 r; asm("mov.b64 %0, {%1, %2};" : "=l"(r) : "f"(lo), "f"(hi)); return r;
}
__device__ __forceinline__ void fma2(u64& d, u64 a, u64 b) {
    asm("fma.rn.f32x2 %0, %1, %2, %0;" : "+l"(d) : "l"(a), "l"(b));
}
__device__ __forceinline__ void add2(u64& d, u64 a) {
    asm("add.rn.f32x2 %0, %0, %1;" : "+l"(d) : "l"(a));
}
__device__ __forceinline__ float2 unpack2(u64 v) {
    float2 f; asm("mov.b64 {%0, %1}, %2;" : "=f"(f.x), "=f"(f.y) : "l"(v)); return f;
}

// ---- device scratch (no cudaMalloc allowed) ----
// g_deg starts zero (static init) and is re-zeroed by gather2 (last reader).
__device__ int    g_deg    [N_MAX];                 // in-degree (self-loop excluded)
__device__ float  g_dinv   [N_MAX];
__device__ int    g_rowstart[N_MAX];
__device__ int    g_cursor [N_MAX];
__device__ int    g_bsum   [NB_MAX];
__device__ int    g_bofs   [NB_MAX];
__device__ int    g_csr    [E_MAX];                 // src index only (dinv folded into features)
__device__ __half g_H1h [(size_t)N_MAX * HID_F];    // dinv[n] * (x @ W1)[n]  (fp16)
__device__ float  g_agg1[(size_t)N_MAX * HID_F];    // relu(agg), fp32
__device__ __half g_H2h [(size_t)N_MAX * OUT_F];    // dinv[n] * (agg1 @ W2)[n] (fp16)

// ---------------------------------------------------------------------------
__global__ void k_edge_prep(const int* __restrict__ ei, int E) {
    int e = blockIdx.x * blockDim.x + threadIdx.x;
    if (e < E) atomicAdd(&g_deg[ei[E + e]], 1);
}

// SA: per-block indegree sums + dinv (deg = indeg + 1 self-loop)
__global__ __launch_bounds__(256) void k_scan_a(int N) {
    __shared__ int sh[256];
    int t = threadIdx.x;
    int n = blockIdx.x * 256 + t;
    int cnt = (n < N) ? g_deg[n] : 0;
    if (n < N) g_dinv[n] = rsqrtf((float)(cnt + 1));
    sh[t] = cnt;
    __syncthreads();
    for (int off = 128; off > 0; off >>= 1) {
        if (t < off) sh[t] += sh[t + off];
        __syncthreads();
    }
    if (t == 0) g_bsum[blockIdx.x] = sh[0];
}

__global__ __launch_bounds__(512) void k_scan_b(int NB) {
    __shared__ int sh[512];
    int t = threadIdx.x;
    int v = (t < NB) ? g_bsum[t] : 0;
    sh[t] = v;
    __syncthreads();
    for (int off = 1; off < 512; off <<= 1) {
        int add = (t >= off) ? sh[t - off] : 0;
        __syncthreads();
        sh[t] += add;
        __syncthreads();
    }
    if (t < NB) g_bofs[t] = sh[t] - v;
}

__global__ __launch_bounds__(256) void k_scan_c(int N) {
    __shared__ int sh[256];
    int t = threadIdx.x;
    int n = blockIdx.x * 256 + t;
    int v = (n < N) ? g_deg[n] : 0;
    sh[t] = v;
    __syncthreads();
    for (int off = 1; off < 256; off <<= 1) {
        int add = (t >= off) ? sh[t - off] : 0;
        __syncthreads();
        sh[t] += add;
        __syncthreads();
    }
    if (n < N) {
        int excl = sh[t] - v + g_bofs[blockIdx.x];
        g_rowstart[n] = excl;
        g_cursor[n]   = excl;
    }
}

// Fill CSR: src index only
__global__ void k_fill(const int* __restrict__ ei, int E) {
    int e = blockIdx.x * blockDim.x + threadIdx.x;
    if (e < E) {
        int s = ei[e];
        int d = ei[E + e];
        int pos = atomicAdd(&g_cursor[d], 1);
        g_csr[pos] = s;
    }
}

// ---------------------------------------------------------------------------
// GEMM1 (tensor cores, fp16 mma.m16n8k16): H1pre = dinv * (x @ W1), fp16 out.
// 256 thr = 8 warps; warp w: rows w*16..w*16+15, all 64 cols.
// xs: x chunk as half2 [row][kword], stride 36 words -> A-frag LDS conflict-free
//     (bank = 4*gr + gc + const).
// Wt: W1 transposed [n][kword] half2, stride 68 -> B-frag LDS conflict-free
//     (bank = 4*gr + gc + const).
#define XS_STRIDE 36   // half2-words per row (32 data + 4 pad)
#define WT_STRIDE 68   // half2-words per col (64 data + 4 pad)
__global__ __launch_bounds__(256) void k_gemm1(const float* __restrict__ x,
                                               const float* __restrict__ W,
                                               int N) {
    __shared__ u32 xs[128 * XS_STRIDE];   // 18.4 KB
    __shared__ u32 Wt[HID_F * WT_STRIDE]; // 17.4 KB
    int t = threadIdx.x;
    int warp = t >> 5, lane = t & 31;
    int gr = lane >> 2, gc = lane & 3;
    int row_base = blockIdx.x * 128 + warp * 16;

    // stage Wt: W[k][n] fp32 -> Wt[n][k/2] half2. coalesced reads over n.
    for (int i = t; i < HID_F * (IN_F / 2); i += 256) {   // i = kw*64 + n
        int kw = i >> 6, n = i & 63;
        float lo = W[(2 * kw) * HID_F + n];
        float hi = W[(2 * kw + 1) * HID_F + n];
        __half2 h = __floats2half2_rn(lo, hi);
        Wt[n * WT_STRIDE + kw] = *(u32*)&h;
    }

    float acc[8][4];
    #pragma unroll
    for (int nt = 0; nt < 8; ++nt)
        #pragma unroll
        for (int c = 0; c < 4; ++c) acc[nt][c] = 0.f;

    #pragma unroll
    for (int kc = 0; kc < IN_F; kc += 64) {
        __syncthreads();
        // stage x chunk: 128 rows x 64 floats -> fp16. coalesced LDG.128.
        for (int i = t; i < 128 * 16; i += 256) {   // i = r*16 + q (q = float4 idx)
            int r = i >> 4, q = i & 15;
            int row = blockIdx.x * 128 + r;
            float4 v = make_float4(0.f, 0.f, 0.f, 0.f);
            if (row < N) v = *(const float4*)&x[(size_t)row * IN_F + kc + q * 4];
            __half2 h0 = __floats2half2_rn(v.x, v.y);
            __half2 h1 = __floats2half2_rn(v.z, v.w);
            *(uint2*)&xs[r * XS_STRIDE + q * 2] =
                make_uint2(*(u32*)&h0, *(u32*)&h1);
        }
        __syncthreads();
        #pragma unroll
        for (int ks = 0; ks < 4; ++ks) {            // 4 x k16 per chunk
            int kw0 = ks * 8;                        // word offset in chunk
            u32 a0 = xs[(warp * 16 + gr)     * XS_STRIDE + kw0 + gc];
            u32 a1 = xs[(warp * 16 + gr + 8) * XS_STRIDE + kw0 + gc];
            u32 a2 = xs[(warp * 16 + gr)     * XS_STRIDE + kw0 + gc + 4];
            u32 a3 = xs[(warp * 16 + gr + 8) * XS_STRIDE + kw0 + gc + 4];
            int kwG = (kc >> 1) + kw0;               // global k-word for Wt
            #pragma unroll
            for (int nt = 0; nt < 8; ++nt) {
                u32 b0 = Wt[(nt * 8 + gr) * WT_STRIDE + kwG + gc];
                u32 b1 = Wt[(nt * 8 + gr) * WT_STRIDE + kwG + gc + 4];
                asm("mma.sync.aligned.m16n8k16.row.col.f32.f16.f16.f32 "
                    "{%0,%1,%2,%3}, {%4,%5,%6,%7}, {%8,%9}, {%0,%1,%2,%3};"
                    : "+f"(acc[nt][0]), "+f"(acc[nt][1]),
                      "+f"(acc[nt][2]), "+f"(acc[nt][3])
                    : "r"(a0), "r"(a1), "r"(a2), "r"(a3), "r"(b0), "r"(b1));
            }
        }
    }
    // epilogue: c0,c1 -> row gr cols (2gc,2gc+1); c2,c3 -> row gr+8
    int r0 = row_base + gr;
    int r1 = r0 + 8;
    if (r0 < N) {
        float dv = g_dinv[r0];
        #pragma unroll
        for (int nt = 0; nt < 8; ++nt) {
            __half2 h = __floats2half2_rn(dv * acc[nt][0], dv * acc[nt][1]);
            *(u32*)&g_H1h[(size_t)r0 * HID_F + nt * 8 + 2 * gc] = *(u32*)&h;
        }
    }
    if (r1 < N) {
        float dv = g_dinv[r1];
        #pragma unroll
        for (int nt = 0; nt < 8; ++nt) {
            __half2 h = __floats2half2_rn(dv * acc[nt][2], dv * acc[nt][3]);
            *(u32*)&g_H1h[(size_t)r1 * HID_F + nt * 8 + 2 * gc] = *(u32*)&h;
        }
    }
}

// GEMM2: H2pre[N,32] = dinv * (agg1[N,64] @ W2[64,32]); fp32 math, fp16 store
__global__ __launch_bounds__(256) void k_gemm2(const float* __restrict__ W, int N) {
    __shared__ float Ws[HID_F * OUT_F];
    __shared__ float xs2[32 * HID_F];
    int t = threadIdx.x;
    for (int i = t; i < HID_F * OUT_F; i += 256) Ws[i] = W[i];

    int row0 = blockIdx.x * 32;
    int rows = N - row0; if (rows > 32) rows = 32;

    const float4* xg  = (const float4*)(g_agg1 + (size_t)row0 * HID_F);
    float4*       xs4 = (float4*)xs2;
    const int NV = 32 * HID_F / 4;
    for (int i = t; i < NV; i += 256) {
        int r = i / (HID_F / 4);
        xs4[i] = (r < rows) ? xg[i] : make_float4(0.f, 0.f, 0.f, 0.f);
    }
    __syncthreads();

    int r = t >> 3;
    int g = (t & 7) * 4;
    if (r < rows) {
        u64 a01 = 0ull, a23 = 0ull;
        #pragma unroll 16
        for (int k = 0; k < HID_F; ++k) {
            float xv = xs2[r * HID_F + k];
            u64 xp  = pack2(xv, xv);
            u64 w01 = *(const u64*)&Ws[k * OUT_F + g];
            u64 w23 = *(const u64*)&Ws[k * OUT_F + g + 2];
            fma2(a01, xp, w01);
            fma2(a23, xp, w23);
        }
        float2 f01 = unpack2(a01);
        float2 f23 = unpack2(a23);
        float dv = g_dinv[row0 + r];
        __half2 h01 = __floats2half2_rn(dv * f01.x, dv * f01.y);
        __half2 h23 = __floats2half2_rn(dv * f23.x, dv * f23.y);
        *(uint2*)&g_H2h[(size_t)(row0 + r) * OUT_F + g] =
            make_uint2(*(u32*)&h01, *(u32*)&h23);
    }
}

// ---------------------------------------------------------------------------
// Gather1: quarter-warp per node (4 nodes/warp), 8 lanes x 8 fp16 feats.
// Weightless inner loop. Epilogue: relu(dinv[n]*acc + b1).
__global__ __launch_bounds__(256) void k_gather1(const float* __restrict__ b1, int N) {
    int w    = (blockIdx.x * blockDim.x + threadIdx.x) >> 5;
    int lane = threadIdx.x & 31;
    int h    = lane >> 3;
    int hl   = lane & 7;
    int n    = 4 * w + h;
    bool active = (n < N);
    int nn = active ? n : 0;

    uint4 sh = *(const uint4*)&g_H1h[(size_t)nn * HID_F + hl * 8];
    float2 s0 = __half22float2(*(__half2*)&sh.x);
    float2 s1 = __half22float2(*(__half2*)&sh.y);
    float2 s2 = __half22float2(*(__half2*)&sh.z);
    float2 s3 = __half22float2(*(__half2*)&sh.w);
    u64 acc0 = pack2(s0.x, s0.y);
    u64 acc1 = pack2(s1.x, s1.y);
    u64 acc2 = pack2(s2.x, s2.y);
    u64 acc3 = pack2(s3.x, s3.y);

    int start = active ? g_rowstart[nn] : 0;
    int cnt   = active ? g_deg[nn] : 0;
    int m = cnt;
    m = max(m, __shfl_xor_sync(0xffffffffu, m, 8));
    m = max(m, __shfl_xor_sync(0xffffffffu, m, 16));

    for (int base = 0; base < m; base += 8) {
        int sl = 0;
        if (base + hl < cnt) sl = g_csr[start + base + hl];
        int remw = m - base; if (remw > 8) remw = 8;
        int remh = cnt - base;
        #pragma unroll 4
        for (int k = 0; k < remw; ++k) {
            int sk = __shfl_sync(0xffffffffu, sl, h * 8 + k);
            if (k < remh) {
                uint4 hv = *(const uint4*)&g_H1h[(size_t)sk * HID_F + hl * 8];
                float2 v0 = __half22float2(*(__half2*)&hv.x);
                float2 v1 = __half22float2(*(__half2*)&hv.y);
                float2 v2 = __half22float2(*(__half2*)&hv.z);
                float2 v3 = __half22float2(*(__half2*)&hv.w);
                add2(acc0, pack2(v0.x, v0.y));
                add2(acc1, pack2(v1.x, v1.y));
                add2(acc2, pack2(v2.x, v2.y));
                add2(acc3, pack2(v3.x, v3.y));
            }
        }
    }
    if (active) {
        float dn = g_dinv[n];
        float4 ba = *(const float4*)&b1[hl * 8];
        float4 bc = *(const float4*)&b1[hl * 8 + 4];
        float2 a0 = unpack2(acc0), a1 = unpack2(acc1);
        float2 a2 = unpack2(acc2), a3 = unpack2(acc3);
        *(float4*)&g_agg1[(size_t)n * HID_F + hl * 8] =
            make_float4(fmaxf(fmaf(dn, a0.x, ba.x), 0.f),
                        fmaxf(fmaf(dn, a0.y, ba.y), 0.f),
                        fmaxf(fmaf(dn, a1.x, ba.z), 0.f),
                        fmaxf(fmaf(dn, a1.y, ba.w), 0.f));
        *(float4*)&g_agg1[(size_t)n * HID_F + hl * 8 + 4] =
            make_float4(fmaxf(fmaf(dn, a2.x, bc.x), 0.f),
                        fmaxf(fmaf(dn, a2.y, bc.y), 0.f),
                        fmaxf(fmaf(dn, a3.x, bc.z), 0.f),
                        fmaxf(fmaf(dn, a3.y, bc.w), 0.f));
    }
}

// Gather2: quarter-warp per node, 8 lanes x 4 fp16 feats, weightless loop,
// writes d_out = dinv[n]*acc + b2; zeroes g_deg (self-cleaning).
__global__ __launch_bounds__(256) void k_gather2(const float* __restrict__ b2,
                                                 float* __restrict__ out, int N) {
    int w    = (blockIdx.x * blockDim.x + threadIdx.x) >> 5;
    int lane = threadIdx.x & 31;
    int h    = lane >> 3;
    int hl   = lane & 7;
    int n    = 4 * w + h;
    bool active = (n < N);
    int nn = active ? n : 0;

    uint2 sh = *(const uint2*)&g_H2h[(size_t)nn * OUT_F + hl * 4];
    float2 s0 = __half22float2(*(__half2*)&sh.x);
    float2 s1 = __half22float2(*(__half2*)&sh.y);
    u64 acc0 = pack2(s0.x, s0.y);
    u64 acc1 = pack2(s1.x, s1.y);

    int start = active ? g_rowstart[nn] : 0;
    int cnt   = active ? g_deg[nn] : 0;
    int m = cnt;
    m = max(m, __shfl_xor_sync(0xffffffffu, m, 8));
    m = max(m, __shfl_xor_sync(0xffffffffu, m, 16));

    for (int base = 0; base < m; base += 8) {
        int sl = 0;
        if (base + hl < cnt) sl = g_csr[start + base + hl];
        int remw = m - base; if (remw > 8) remw = 8;
        int remh = cnt - base;
        #pragma unroll 4
        for (int k = 0; k < remw; ++k) {
            int sk = __shfl_sync(0xffffffffu, sl, h * 8 + k);
            if (k < remh) {
                uint2 hv = *(const uint2*)&g_H2h[(size_t)sk * OUT_F + hl * 4];
                float2 v0 = __half22float2(*(__half2*)&hv.x);
                float2 v1 = __half22float2(*(__half2*)&hv.y);
                add2(acc0, pack2(v0.x, v0.y));
                add2(acc1, pack2(v1.x, v1.y));
            }
        }
    }
    if (active) {
        float dn = g_dinv[n];
        float4 bb = *(const float4*)&b2[hl * 4];
        float2 a0 = unpack2(acc0), a1 = unpack2(acc1);
        *(float4*)&out[(size_t)n * OUT_F + hl * 4] =
            make_float4(fmaf(dn, a0.x, bb.x), fmaf(dn, a0.y, bb.y),
                        fmaf(dn, a1.x, bb.z), fmaf(dn, a1.y, bb.w));
        if (hl == 0) g_deg[n] = 0;    // restore invariant for next launch
    }
}

// ---------------------------------------------------------------------------
extern "C" void kernel_launch(void* const* d_in, const int* in_sizes, int n_in,
                              void* d_out, int out_size) {
    const float* x  = (const float*)d_in[0];
    const int*   ei = (const int*)d_in[1];      // int32 (JAX x64 disabled)
    const float* W1 = (const float*)d_in[2];
    const float* b1 = (const float*)d_in[3];
    const float* W2 = (const float*)d_in[4];
    const float* b2 = (const float*)d_in[5];
    float*       out = (float*)d_out;

    const int N = in_sizes[0] / IN_F;     // 100000
    const int E = in_sizes[1] / 2;        // 1600000
    const int NB = (N + 255) / 256;

    const int T = 256;
    k_edge_prep<<<(E + T - 1) / T, T>>>(ei, E);     // deg starts zero
    k_scan_a<<<NB, 256>>>(N);                       // computes dinv
    k_scan_b<<<1, 512>>>(NB);
    k_gemm1  <<<(N + 127) / 128, 256>>>(x, W1, N);  // 4th launch (profiled; needs dinv)
    k_scan_c<<<NB, 256>>>(N);
    k_fill  <<<(E + T - 1) / T, T>>>(ei, E);

    k_gather1<<<(N + 31) / 32, 256>>>(b1, N);

    k_gemm2  <<<(N + 31) / 32, 256>>>(W2, N);
    k_gather2<<<(N + 31) / 32, 256>>>(b2, out, N);  // zeroes g_deg at end
}